// round 4
// baseline (speedup 1.0000x reference)
#include <cuda_runtime.h>
#include <math.h>

// B=2 N=512 CS=384 CZ=128 H=12 D=16 P=4 PV=8
// NPROJ=1152 (q 0..191 | k 192..383 | v 384..575 | qp 576..719 | kp 720..863 | vp 864..1151)
// CAT=2112 (o_hat 0..1535 | o 1536..1727 | o_hp 1728..2015 | norm 2016..2111)

__device__ float WPROJ[384 * 1152];
__device__ float PROJ[1024 * 1152];
__device__ float QQb[1024 * 384];
__device__ float KKb[1024 * 384];
__device__ float TVb[1024 * 288];
__device__ float CATb[1024 * 2112];

// ---------------- K1: pack projection weights ----------------
__global__ void kpack(const float* __restrict__ wq, const float* __restrict__ wk,
                      const float* __restrict__ wv, const float* __restrict__ wqp,
                      const float* __restrict__ wkp, const float* __restrict__ wvp) {
    int e = blockIdx.x * 256 + threadIdx.x;  // 1728*256 = 442368 = 384*1152
    int c = e / 1152, col = e - c * 1152;
    float v;
    if (col < 192)       v = wq[c * 192 + col];
    else if (col < 384)  v = wk[c * 192 + col - 192];
    else if (col < 576)  v = wv[c * 192 + col - 384];
    else if (col < 720)  v = wqp[c * 144 + col - 576];
    else if (col < 864)  v = wkp[c * 144 + col - 720];
    else                 v = wvp[c * 288 + col - 864];
    WPROJ[e] = v;
}

// ---------------- K2/K5: tiled SGEMM (all dims divide tiles) ----------------
__global__ __launch_bounds__(256)
void sgemm_k(const float* __restrict__ A, const float* __restrict__ Bm,
             float* __restrict__ C, int M, int Nn, int K,
             const float* __restrict__ bias) {
    const int BM = 64, BN = 64, BK = 16, TM = 4, TN = 4;
    __shared__ float As[BK][BM];
    __shared__ float Bs[BK][BN];
    int t = threadIdx.x;
    int tx = t % (BN / TN), ty = t / (BN / TN);
    int row0 = blockIdx.y * BM, col0 = blockIdx.x * BN;
    float acc[TM][TN] = {};
    for (int k0 = 0; k0 < K; k0 += BK) {
        __syncthreads();
        {   // A tile: 256 float4, one per thread (transposed store)
            int r = t / 4, kk = (t % 4) * 4;
            float4 v = *(const float4*)(A + (size_t)(row0 + r) * K + k0 + kk);
            As[kk][r] = v.x; As[kk + 1][r] = v.y; As[kk + 2][r] = v.z; As[kk + 3][r] = v.w;
        }
        {   // B tile: 256 float4
            int kk = t / 16, n4 = (t % 16) * 4;
            *(float4*)(&Bs[kk][n4]) = *(const float4*)(Bm + (size_t)(k0 + kk) * Nn + col0 + n4);
        }
        __syncthreads();
#pragma unroll
        for (int kk = 0; kk < BK; kk++) {
            float ra[TM], rb[TN];
#pragma unroll
            for (int u = 0; u < TM; u++) ra[u] = As[kk][ty * TM + u];
#pragma unroll
            for (int v = 0; v < TN; v++) rb[v] = Bs[kk][tx * TN + v];
#pragma unroll
            for (int u = 0; u < TM; u++)
#pragma unroll
                for (int v = 0; v < TN; v++) acc[u][v] += ra[u] * rb[v];
        }
    }
#pragma unroll
    for (int u = 0; u < TM; u++) {
        int r = row0 + ty * TM + u;
#pragma unroll
        for (int v = 0; v < TN; v++) {
            int cc = col0 + tx * TN + v;
            float val = acc[u][v];
            if (bias) val += bias[cc];
            C[(size_t)r * Nn + cc] = val;
        }
    }
}

// ---------------- K3: rigid transforms + QQ/KK/TV packing ----------------
__global__ void ktransform(const float* __restrict__ rots, const float* __restrict__ trans,
                           const float* __restrict__ gamma) {
    int row = blockIdx.x;
    int h = threadIdx.x;
    if (h >= 12) return;
    const float* pr = PROJ + (size_t)row * 1152;
    float R0 = rots[row * 9 + 0], R1 = rots[row * 9 + 1], R2 = rots[row * 9 + 2];
    float R3 = rots[row * 9 + 3], R4 = rots[row * 9 + 4], R5 = rots[row * 9 + 5];
    float R6 = rots[row * 9 + 6], R7 = rots[row * 9 + 7], R8 = rots[row * 9 + 8];
    float t0 = trans[row * 3 + 0], t1 = trans[row * 3 + 1], t2 = trans[row * 3 + 2];
    float* QQ = QQb + (size_t)row * 384 + h * 32;
    float* KK = KKb + (size_t)row * 384 + h * 32;
    float cg = 0.11785113019775793f * gamma[h];  // 0.5 * sqrt(2/36) * gamma
#pragma unroll
    for (int d = 0; d < 16; d++) {
        QQ[d] = pr[h * 16 + d] * 0.25f;          // fold 1/sqrt(D)
        KK[d] = pr[192 + h * 16 + d];
    }
    float sq2 = 0.f, sk2 = 0.f;
#pragma unroll
    for (int p = 0; p < 4; p++) {
        const float* qp = pr + 576 + h * 12 + p * 3;
        float x = qp[0], y = qp[1], zz = qp[2];
        float gx = R0 * x + R1 * y + R2 * zz + t0;
        float gy = R3 * x + R4 * y + R5 * zz + t1;
        float gz = R6 * x + R7 * y + R8 * zz + t2;
        QQ[16 + p * 3 + 0] = 2.f * cg * gx;
        QQ[16 + p * 3 + 1] = 2.f * cg * gy;
        QQ[16 + p * 3 + 2] = 2.f * cg * gz;
        sq2 += gx * gx + gy * gy + gz * gz;
        const float* kp = pr + 720 + h * 12 + p * 3;
        x = kp[0]; y = kp[1]; zz = kp[2];
        gx = R0 * x + R1 * y + R2 * zz + t0;
        gy = R3 * x + R4 * y + R5 * zz + t1;
        gz = R6 * x + R7 * y + R8 * zz + t2;
        KK[16 + p * 3 + 0] = gx; KK[16 + p * 3 + 1] = gy; KK[16 + p * 3 + 2] = gz;
        sk2 += gx * gx + gy * gy + gz * gz;
    }
    QQ[28] = -cg;       KK[28] = sk2;
    QQ[29] = -cg * sq2; KK[29] = 1.f;
    QQ[30] = 0.f; QQ[31] = 0.f; KK[30] = 0.f; KK[31] = 0.f;
    float* tp = TVb + (size_t)row * 288 + h * 24;
#pragma unroll
    for (int p = 0; p < 8; p++) {
        const float* vp = pr + 864 + h * 24 + p * 3;
        float x = vp[0], y = vp[1], zz = vp[2];
        tp[p * 3 + 0] = R0 * x + R1 * y + R2 * zz + t0;
        tp[p * 3 + 1] = R3 * x + R4 * y + R5 * zz + t1;
        tp[p * 3 + 2] = R6 * x + R7 * y + R8 * zz + t2;
    }
}

// ---------------- K4: fused attention (bias GEMM + logits + softmax + aggregation) ----------------
__global__ __launch_bounds__(512)
void kattn(const float* __restrict__ z, const float* __restrict__ wb,
           const float* __restrict__ rots, const float* __restrict__ trans) {
    __shared__ float lg[512 * 12];     // logits -> exp weights
    __shared__ float wbs[128 * 12];
    __shared__ float QQs[384];
    __shared__ float rinv[12];
    __shared__ float hp_s[288];
    __shared__ float Rt[12];
    int t = threadIdx.x;
    int row = blockIdx.x;              // b*512 + i
    int b0 = (row >> 9) << 9;
    const float* zrow = z + (size_t)row * 512 * 128;
    for (int i = t; i < 1536; i += 512) wbs[i] = wb[i];
    if (t < 384) QQs[t] = QQb[(size_t)row * 384 + t];
    if (t < 9) Rt[t] = rots[row * 9 + t];
    else if (t < 12) Rt[t] = trans[row * 3 + t - 9];
    __syncthreads();

    // ---- Pass 1: j = t; bias + dot32 logits for 12 heads ----
    {
        int j = t;
        float acc[12] = {};
        const float4* zp = (const float4*)(zrow + j * 128);
        const float4* wb4 = (const float4*)wbs;
#pragma unroll 2
        for (int c4 = 0; c4 < 32; c4++) {
            float4 zv = zp[c4];
#pragma unroll
            for (int u = 0; u < 4; u++) {
                float zc = u == 0 ? zv.x : u == 1 ? zv.y : u == 2 ? zv.z : zv.w;
                int cc = (c4 * 4 + u) * 3;
                float4 w0 = wb4[cc], w1 = wb4[cc + 1], w2 = wb4[cc + 2];
                acc[0] += zc * w0.x; acc[1] += zc * w0.y; acc[2] += zc * w0.z; acc[3] += zc * w0.w;
                acc[4] += zc * w1.x; acc[5] += zc * w1.y; acc[6] += zc * w1.z; acc[7] += zc * w1.w;
                acc[8] += zc * w2.x; acc[9] += zc * w2.y; acc[10] += zc * w2.z; acc[11] += zc * w2.w;
            }
        }
        const float4* kk = (const float4*)(KKb + (size_t)(b0 + j) * 384);
        const float4* qq4 = (const float4*)QQs;
#pragma unroll
        for (int h = 0; h < 12; h++) {
            float d = 0.f;
#pragma unroll
            for (int u = 0; u < 8; u++) {
                float4 a4 = qq4[h * 8 + u], b4 = kk[h * 8 + u];
                d += a4.x * b4.x + a4.y * b4.y + a4.z * b4.z + a4.w * b4.w;
            }
            lg[j * 12 + h] = 0.5773502691896258f * (acc[h] + d);
        }
    }
    __syncthreads();

    // ---- Softmax: warp w handles head w ----
    {
        int w = t >> 5, l = t & 31;
        if (w < 12) {
            float m = -1e30f;
            for (int jj = l; jj < 512; jj += 32) m = fmaxf(m, lg[jj * 12 + w]);
#pragma unroll
            for (int o = 16; o; o >>= 1) m = fmaxf(m, __shfl_xor_sync(0xffffffffu, m, o));
            float s = 0.f;
            for (int jj = l; jj < 512; jj += 32) {
                float e = __expf(lg[jj * 12 + w] - m);
                lg[jj * 12 + w] = e;
                s += e;
            }
#pragma unroll
            for (int o = 16; o; o >>= 1) s += __shfl_xor_sync(0xffffffffu, s, o);
            if (l == 0) rinv[w] = 1.f / s;
        }
    }
    __syncthreads();

    float* cat = CATb + (size_t)row * 2112;

    // ---- Pass 2a: o_hat = sum_j a*z  (thread = (d, head-group of 3)) ----
    {
        int d = t & 127, g = t >> 7;   // g in 0..3, heads g, g+4, g+8
        float a0 = 0.f, a1 = 0.f, a2 = 0.f;
        const float* zc = zrow + d;
#pragma unroll 4
        for (int j = 0; j < 512; j++) {
            float zv = __ldg(zc + j * 128);
            const float* aj = &lg[j * 12];
            a0 += aj[g] * zv; a1 += aj[g + 4] * zv; a2 += aj[g + 8] * zv;
        }
        cat[g * 128 + d]       = a0 * rinv[g];
        cat[(g + 4) * 128 + d] = a1 * rinv[g + 4];
        cat[(g + 8) * 128 + d] = a2 * rinv[g + 8];
    }

    // ---- Pass 2b: o (192 outputs) and point values (288 outputs) ----
    if (t < 192) {
        int h = t >> 4;
        float a = 0.f;
        const float* src = PROJ + (size_t)b0 * 1152 + 384 + t;
#pragma unroll 4
        for (int j = 0; j < 512; j++)
            a += lg[j * 12 + h] * __ldg(src + (size_t)j * 1152);
        cat[1536 + t] = a * rinv[h];
    } else if (t < 480) {
        int e = t - 192;            // h*24 + p*3 + x
        int h = e / 24;
        float a = 0.f;
        const float* src = TVb + (size_t)b0 * 288 + e;
#pragma unroll 4
        for (int j = 0; j < 512; j++)
            a += lg[j * 12 + h] * __ldg(src + (size_t)j * 288);
        hp_s[e] = a * rinv[h];
    }
    __syncthreads();

    // ---- Epilogue: rigid invert + norms (thread = (h,p), 96 threads) ----
    if (t < 96) {
        float gx = hp_s[t * 3 + 0] - Rt[9];
        float gy = hp_s[t * 3 + 1] - Rt[10];
        float gz = hp_s[t * 3 + 2] - Rt[11];
        float lx = Rt[0] * gx + Rt[3] * gy + Rt[6] * gz;
        float ly = Rt[1] * gx + Rt[4] * gy + Rt[7] * gz;
        float lz = Rt[2] * gx + Rt[5] * gy + Rt[8] * gz;
        cat[1728 + t * 3 + 0] = lx;
        cat[1728 + t * 3 + 1] = ly;
        cat[1728 + t * 3 + 2] = lz;
        cat[2016 + t] = sqrtf(lx * lx + ly * ly + lz * lz);
    }
}

extern "C" void kernel_launch(void* const* d_in, const int* in_sizes, int n_in,
                              void* d_out, int out_size) {
    const float* s_i   = (const float*)d_in[0];
    const float* z_ij  = (const float*)d_in[1];
    const float* rots  = (const float*)d_in[2];
    const float* trans = (const float*)d_in[3];
    const float* wq    = (const float*)d_in[4];
    const float* wk    = (const float*)d_in[5];
    const float* wv    = (const float*)d_in[6];
    const float* wqp   = (const float*)d_in[7];
    const float* wkp   = (const float*)d_in[8];
    const float* wvp   = (const float*)d_in[9];
    const float* wb    = (const float*)d_in[10];
    const float* gamma = (const float*)d_in[11];
    const float* wout  = (const float*)d_in[12];
    const float* bout  = (const float*)d_in[13];
    float* out = (float*)d_out;

    float* dWPROJ; cudaGetSymbolAddress((void**)&dWPROJ, WPROJ);
    float* dPROJ;  cudaGetSymbolAddress((void**)&dPROJ, PROJ);
    float* dCAT;   cudaGetSymbolAddress((void**)&dCAT, CATb);

    kpack<<<1728, 256>>>(wq, wk, wv, wqp, wkp, wvp);
    {   // PROJ = s_i @ WPROJ : M=1024 N=1152 K=384
        dim3 g(1152 / 64, 1024 / 64);
        sgemm_k<<<g, 256>>>(s_i, dWPROJ, dPROJ, 1024, 1152, 384, nullptr);
    }
    ktransform<<<1024, 32>>>(rots, trans, gamma);
    kattn<<<1024, 512>>>(z_ij, wb, rots, trans);
    {   // out = CAT @ wout + bout : M=1024 N=384 K=2112
        dim3 g(384 / 64, 1024 / 64);
        sgemm_k<<<g, 256>>>(dCAT, wout, out, 1024, 384, 2112, bout);
    }
}

// round 5
// speedup vs baseline: 1.7150x; 1.7150x over previous
#include <cuda_runtime.h>
#include <math.h>

// B=2 N=512 CS=384 CZ=128 H=12 D=16 P=4 PV=8
// PROJ cols: q 0..191 | k 192..383 | v 384..575 | qp 576..719 | kp 720..863 | vp 864..1151
// CAT=2112: o_hat 0..1535 | o 1536..1727 | o_hp 1728..2015 | norm 2016..2111

__device__ float WPROJ[384 * 1152];
__device__ float PROJ[1024 * 1152];
__device__ float QQb[1024 * 384];
__device__ float KKb[1024 * 384];
__device__ float TVb[1024 * 288];
__device__ float CATb[1024 * 2112];
__device__ float SCA[2 * 12 * 512 * 512];   // scores, then normalized attention (in-place per row)
__device__ float OHP[1024 * 288];           // global-frame point aggregation

// ---------------- K1: pack projection weights ----------------
__global__ void kpack(const float* __restrict__ wq, const float* __restrict__ wk,
                      const float* __restrict__ wv, const float* __restrict__ wqp,
                      const float* __restrict__ wkp, const float* __restrict__ wvp) {
    int e = blockIdx.x * 256 + threadIdx.x;  // 1728*256 = 442368 = 384*1152
    int c = e / 1152, col = e - c * 1152;
    float v;
    if (col < 192)       v = wq[c * 192 + col];
    else if (col < 384)  v = wk[c * 192 + col - 192];
    else if (col < 576)  v = wv[c * 192 + col - 384];
    else if (col < 720)  v = wqp[c * 144 + col - 576];
    else if (col < 864)  v = wkp[c * 144 + col - 720];
    else                 v = wvp[c * 288 + col - 864];
    WPROJ[e] = v;
}

// ---------------- tiled SGEMM (all dims divide tiles) ----------------
__global__ __launch_bounds__(256)
void sgemm_k(const float* __restrict__ A, const float* __restrict__ Bm,
             float* __restrict__ C, int M, int Nn, int K,
             const float* __restrict__ bias) {
    const int BK = 16;
    __shared__ float As[BK][64];
    __shared__ float Bs[BK][64];
    int t = threadIdx.x;
    int tx = t % 16, ty = t / 16;
    int row0 = blockIdx.y * 64, col0 = blockIdx.x * 64;
    float acc[4][4] = {};
    for (int k0 = 0; k0 < K; k0 += BK) {
        __syncthreads();
        {
            int r = t / 4, kk = (t % 4) * 4;
            float4 v = *(const float4*)(A + (size_t)(row0 + r) * K + k0 + kk);
            As[kk][r] = v.x; As[kk + 1][r] = v.y; As[kk + 2][r] = v.z; As[kk + 3][r] = v.w;
        }
        {
            int kk = t / 16, n4 = (t % 16) * 4;
            *(float4*)(&Bs[kk][n4]) = *(const float4*)(Bm + (size_t)(k0 + kk) * Nn + col0 + n4);
        }
        __syncthreads();
#pragma unroll
        for (int kk = 0; kk < BK; kk++) {
            float ra[4], rb[4];
#pragma unroll
            for (int u = 0; u < 4; u++) ra[u] = As[kk][ty * 4 + u];
#pragma unroll
            for (int v = 0; v < 4; v++) rb[v] = Bs[kk][tx * 4 + v];
#pragma unroll
            for (int u = 0; u < 4; u++)
#pragma unroll
                for (int v = 0; v < 4; v++) acc[u][v] += ra[u] * rb[v];
        }
    }
#pragma unroll
    for (int u = 0; u < 4; u++) {
        int r = row0 + ty * 4 + u;
#pragma unroll
        for (int v = 0; v < 4; v++) {
            int cc = col0 + tx * 4 + v;
            float val = acc[u][v];
            if (bias) val += bias[cc];
            C[(size_t)r * Nn + cc] = val;
        }
    }
}

// ---------------- K3: rigid transforms + QQ/KK/TV packing ----------------
__global__ void ktransform(const float* __restrict__ rots, const float* __restrict__ trans,
                           const float* __restrict__ gamma) {
    int row = blockIdx.x;
    int h = threadIdx.x;
    if (h >= 12) return;
    const float* pr = PROJ + (size_t)row * 1152;
    float R0 = rots[row * 9 + 0], R1 = rots[row * 9 + 1], R2 = rots[row * 9 + 2];
    float R3 = rots[row * 9 + 3], R4 = rots[row * 9 + 4], R5 = rots[row * 9 + 5];
    float R6 = rots[row * 9 + 6], R7 = rots[row * 9 + 7], R8 = rots[row * 9 + 8];
    float t0 = trans[row * 3 + 0], t1 = trans[row * 3 + 1], t2 = trans[row * 3 + 2];
    float* QQ = QQb + (size_t)row * 384 + h * 32;
    float* KK = KKb + (size_t)row * 384 + h * 32;
    float cg = 0.11785113019775793f * gamma[h];  // 0.5 * sqrt(2/36) * gamma
#pragma unroll
    for (int d = 0; d < 16; d++) {
        QQ[d] = pr[h * 16 + d] * 0.25f;          // fold 1/sqrt(D)
        KK[d] = pr[192 + h * 16 + d];
    }
    float sq2 = 0.f, sk2 = 0.f;
#pragma unroll
    for (int p = 0; p < 4; p++) {
        const float* qp = pr + 576 + h * 12 + p * 3;
        float x = qp[0], y = qp[1], zz = qp[2];
        float gx = R0 * x + R1 * y + R2 * zz + t0;
        float gy = R3 * x + R4 * y + R5 * zz + t1;
        float gz = R6 * x + R7 * y + R8 * zz + t2;
        QQ[16 + p * 3 + 0] = 2.f * cg * gx;
        QQ[16 + p * 3 + 1] = 2.f * cg * gy;
        QQ[16 + p * 3 + 2] = 2.f * cg * gz;
        sq2 += gx * gx + gy * gy + gz * gz;
        const float* kp = pr + 720 + h * 12 + p * 3;
        x = kp[0]; y = kp[1]; zz = kp[2];
        gx = R0 * x + R1 * y + R2 * zz + t0;
        gy = R3 * x + R4 * y + R5 * zz + t1;
        gz = R6 * x + R7 * y + R8 * zz + t2;
        KK[16 + p * 3 + 0] = gx; KK[16 + p * 3 + 1] = gy; KK[16 + p * 3 + 2] = gz;
        sk2 += gx * gx + gy * gy + gz * gz;
    }
    QQ[28] = -cg;       KK[28] = sk2;
    QQ[29] = -cg * sq2; KK[29] = 1.f;
    QQ[30] = 0.f; QQ[31] = 0.f; KK[30] = 0.f; KK[31] = 0.f;
    float* tp = TVb + (size_t)row * 288 + h * 24;
#pragma unroll
    for (int p = 0; p < 8; p++) {
        const float* vp = pr + 864 + h * 24 + p * 3;
        float x = vp[0], y = vp[1], zz = vp[2];
        tp[p * 3 + 0] = R0 * x + R1 * y + R2 * zz + t0;
        tp[p * 3 + 1] = R3 * x + R4 * y + R5 * zz + t1;
        tp[p * 3 + 2] = R6 * x + R7 * y + R8 * zz + t2;
    }
}

// ---------------- K4: score GEMM  SC[bh][i][j] = QQ[i,h,:].KK[j,h,:] (K=32) ----------------
__global__ __launch_bounds__(256) void kscore() {
    __shared__ float As[32][68];
    __shared__ float Bs[32][68];
    int t = threadIdx.x;
    int bh = blockIdx.z, b = bh / 12, h = bh % 12;
    int i0 = blockIdx.y * 64, j0 = blockIdx.x * 64;
#pragma unroll
    for (int s = 0; s < 2; s++) {
        int idx = t + s * 256;
        int r = idx >> 3, c4 = (idx & 7) * 4;
        float4 va = *(const float4*)(QQb + (size_t)(b * 512 + i0 + r) * 384 + h * 32 + c4);
        As[c4][r] = va.x; As[c4 + 1][r] = va.y; As[c4 + 2][r] = va.z; As[c4 + 3][r] = va.w;
        float4 vb = *(const float4*)(KKb + (size_t)(b * 512 + j0 + r) * 384 + h * 32 + c4);
        Bs[c4][r] = vb.x; Bs[c4 + 1][r] = vb.y; Bs[c4 + 2][r] = vb.z; Bs[c4 + 3][r] = vb.w;
    }
    __syncthreads();
    int tx = t & 15, ty = t >> 4;
    float acc[4][4] = {};
#pragma unroll
    for (int kk = 0; kk < 32; kk++) {
        float ra[4], rb[4];
#pragma unroll
        for (int u = 0; u < 4; u++) ra[u] = As[kk][ty * 4 + u];
#pragma unroll
        for (int v = 0; v < 4; v++) rb[v] = Bs[kk][tx * 4 + v];
#pragma unroll
        for (int u = 0; u < 4; u++)
#pragma unroll
            for (int v = 0; v < 4; v++) acc[u][v] += ra[u] * rb[v];
    }
#pragma unroll
    for (int u = 0; u < 4; u++) {
        float4 o = make_float4(acc[u][0], acc[u][1], acc[u][2], acc[u][3]);
        *(float4*)(SCA + ((size_t)bh * 512 + i0 + ty * 4 + u) * 512 + j0 + tx * 4) = o;
    }
}

// ---------------- K5: fused attention per (b,i): bias + softmax + o_hat + A write ----------------
// dyn smem: zs 128*132 | lg 512*13 | wbT 12*128 | rinv 12   (~100.4 KB)
__global__ __launch_bounds__(512)
void kattn(const float* __restrict__ z, const float* __restrict__ wb) {
    extern __shared__ float sm[];
    float* zs = sm;                    // 16896 floats (also reused as "part")
    float* lg = sm + 16896;            // 6656
    float* wbT = sm + 23552;           // 1536
    float* rinv = sm + 25088;          // 12
    int t = threadIdx.x;
    int row = blockIdx.x, b = row >> 9, i = row & 511;
    const float* zrow = z + (size_t)row * 65536;

    for (int e = t; e < 1536; e += 512) {
        int h = e >> 7, c = e & 127;
        wbT[e] = wb[c * 12 + h];
    }

    int jl = t & 127, g = t >> 7;
    const float4* w0 = (const float4*)(wbT + g * 128);
    const float4* w1 = (const float4*)(wbT + (g + 4) * 128);
    const float4* w2 = (const float4*)(wbT + (g + 8) * 128);

    // ---- Pass 1: bias GEMV from smem-staged z + precomputed score ----
    for (int tile = 0; tile < 4; tile++) {
        __syncthreads();
#pragma unroll
        for (int s = 0; s < 8; s++) {
            int idx = t + s * 512;
            int r = idx >> 5, c4 = idx & 31;
            float4 v = *(const float4*)(zrow + (size_t)(tile * 128 + r) * 128 + c4 * 4);
            *(float4*)(zs + r * 132 + c4 * 4) = v;
        }
        __syncthreads();
        float a0 = 0.f, a1 = 0.f, a2 = 0.f;
        const float4* zv4 = (const float4*)(zs + jl * 132);
#pragma unroll
        for (int c4 = 0; c4 < 32; c4++) {
            float4 zq = zv4[c4];
            float4 x0 = w0[c4], x1 = w1[c4], x2 = w2[c4];
            a0 += zq.x * x0.x + zq.y * x0.y + zq.z * x0.z + zq.w * x0.w;
            a1 += zq.x * x1.x + zq.y * x1.y + zq.z * x1.z + zq.w * x1.w;
            a2 += zq.x * x2.x + zq.y * x2.y + zq.z * x2.z + zq.w * x2.w;
        }
        int j = tile * 128 + jl;
        size_t pl = (size_t)512 * 512;
        size_t base = ((size_t)(b * 12) * 512 + i) * 512 + j;
        float s0 = SCA[base + (size_t)g * pl];
        float s1 = SCA[base + (size_t)(g + 4) * pl];
        float s2 = SCA[base + (size_t)(g + 8) * pl];
        const float WL = 0.5773502691896258f;
        lg[j * 13 + g]     = WL * (a0 + s0);
        lg[j * 13 + g + 4] = WL * (a1 + s1);
        lg[j * 13 + g + 8] = WL * (a2 + s2);
    }
    __syncthreads();

    // ---- Softmax: warp w handles head w ----
    {
        int w = t >> 5, l = t & 31;
        if (w < 12) {
            float m = -1e30f;
            for (int jj = l; jj < 512; jj += 32) m = fmaxf(m, lg[jj * 13 + w]);
#pragma unroll
            for (int o = 16; o; o >>= 1) m = fmaxf(m, __shfl_xor_sync(0xffffffffu, m, o));
            float s = 0.f;
            for (int jj = l; jj < 512; jj += 32) {
                float e = __expf(lg[jj * 13 + w] - m);
                lg[jj * 13 + w] = e;
                s += e;
            }
#pragma unroll
            for (int o = 16; o; o >>= 1) s += __shfl_xor_sync(0xffffffffu, s, o);
            if (l == 0) rinv[w] = 1.f / s;
        }
    }
    __syncthreads();

    // ---- Write normalized attention planes (in-place over SC) ----
    {
        int j = t;
        size_t pl = (size_t)512 * 512;
        size_t base = ((size_t)(b * 12) * 512 + i) * 512 + j;
#pragma unroll
        for (int h = 0; h < 12; h++)
            SCA[base + (size_t)h * pl] = lg[j * 13 + h] * rinv[h];
    }

    // ---- Pass 2: o_hat = sum_j a*z, j-quartered, combine in smem ----
    int d = t & 127, jq = t >> 7;
    float acc[12] = {};
    const float* zc = zrow + (size_t)jq * 16384 + d;
    const float* lgp = lg + (size_t)jq * 128 * 13;
#pragma unroll 2
    for (int jj = 0; jj < 128; jj++) {
        float zv = __ldg(zc + jj * 128);
        const float* aj = lgp + jj * 13;
#pragma unroll
        for (int h = 0; h < 12; h++) acc[h] += aj[h] * zv;
    }
    __syncthreads();   // zs free (pass1 done) -> reuse as partials
    float* part = zs;  // [(jq*128+d)*13 + h]
#pragma unroll
    for (int h = 0; h < 12; h++) part[(jq * 128 + d) * 13 + h] = acc[h];
    __syncthreads();
    float* cat = CATb + (size_t)row * 2112;
#pragma unroll
    for (int u = 0; u < 3; u++) {
        int e = t + u * 512;
        int h = e >> 7, dd = e & 127;
        float s = part[dd * 13 + h] + part[(128 + dd) * 13 + h] +
                  part[(256 + dd) * 13 + h] + part[(384 + dd) * 13 + h];
        cat[h * 128 + dd] = s * rinv[h];
    }
}

// ---------------- K6: value aggregation GEMMs  A[bh] x [v|tv] ----------------
__global__ __launch_bounds__(256) void kagg() {
    __shared__ float As[64 * 68];   // [i][j], pitch 68
    __shared__ float Bs[64 * 41];   // [j][c], c<16 -> v, else tv
    int t = threadIdx.x;
    int bh = blockIdx.y, b = bh / 12, h = bh % 12;
    int i0 = blockIdx.x * 64;
    int il = t & 63, cp = t >> 6;
    float acc[10] = {};
    for (int jt = 0; jt < 8; jt++) {
        __syncthreads();
#pragma unroll
        for (int s = 0; s < 4; s++) {
            int idx = t + s * 256;
            int r = idx >> 4, j4 = (idx & 15) * 4;
            float4 v = *(const float4*)(SCA + ((size_t)bh * 512 + i0 + r) * 512 + jt * 64 + j4);
            *(float4*)(As + r * 68 + j4) = v;
        }
#pragma unroll
        for (int s = 0; s < 10; s++) {
            int idx = t + s * 256;
            int jj = idx / 40, c = idx - jj * 40;
            int jg = b * 512 + jt * 64 + jj;
            float v = (c < 16) ? PROJ[(size_t)jg * 1152 + 384 + h * 16 + c]
                               : TVb[(size_t)jg * 288 + h * 24 + (c - 16)];
            Bs[jj * 41 + c] = v;
        }
        __syncthreads();
        const float4* a4 = (const float4*)(As + il * 68);
#pragma unroll
        for (int j4 = 0; j4 < 16; j4++) {
            float4 av = a4[j4];
#pragma unroll
            for (int u = 0; u < 4; u++) {
                float a = u == 0 ? av.x : u == 1 ? av.y : u == 2 ? av.z : av.w;
                const float* brow = Bs + (j4 * 4 + u) * 41 + cp;
#pragma unroll
                for (int cc = 0; cc < 10; cc++) acc[cc] += a * brow[cc * 4];
            }
        }
    }
    size_t crow = (size_t)(b * 512 + i0 + il);
#pragma unroll
    for (int cc = 0; cc < 10; cc++) {
        int col = cp + cc * 4;
        if (col < 16) CATb[crow * 2112 + 1536 + h * 16 + col] = acc[cc];
        else          OHP[crow * 288 + h * 24 + (col - 16)] = acc[cc];
    }
}

// ---------------- K7: rigid invert + norms ----------------
__global__ void kepi(const float* __restrict__ rots, const float* __restrict__ trans) {
    __shared__ float R[9], T[3];
    int row = blockIdx.x, t = threadIdx.x;   // 96 threads
    if (t < 9) R[t] = rots[row * 9 + t];
    if (t < 3) T[t] = trans[row * 3 + t];
    __syncthreads();
    int h = t >> 3, p = t & 7;
    size_t base = (size_t)row * 288 + h * 24 + p * 3;
    float gx = OHP[base + 0] - T[0];
    float gy = OHP[base + 1] - T[1];
    float gz = OHP[base + 2] - T[2];
    float lx = R[0] * gx + R[3] * gy + R[6] * gz;
    float ly = R[1] * gx + R[4] * gy + R[7] * gz;
    float lz = R[2] * gx + R[5] * gy + R[8] * gz;
    float* cat = CATb + (size_t)row * 2112;
    cat[1728 + t * 3 + 0] = lx;
    cat[1728 + t * 3 + 1] = ly;
    cat[1728 + t * 3 + 2] = lz;
    cat[2016 + t] = sqrtf(lx * lx + ly * ly + lz * lz);
}

extern "C" void kernel_launch(void* const* d_in, const int* in_sizes, int n_in,
                              void* d_out, int out_size) {
    const float* s_i   = (const float*)d_in[0];
    const float* z_ij  = (const float*)d_in[1];
    const float* rots  = (const float*)d_in[2];
    const float* trans = (const float*)d_in[3];
    const float* wq    = (const float*)d_in[4];
    const float* wk    = (const float*)d_in[5];
    const float* wv    = (const float*)d_in[6];
    const float* wqp   = (const float*)d_in[7];
    const float* wkp   = (const float*)d_in[8];
    const float* wvp   = (const float*)d_in[9];
    const float* wb    = (const float*)d_in[10];
    const float* gamma = (const float*)d_in[11];
    const float* wout  = (const float*)d_in[12];
    const float* bout  = (const float*)d_in[13];
    float* out = (float*)d_out;

    float* dWPROJ; cudaGetSymbolAddress((void**)&dWPROJ, WPROJ);
    float* dPROJ;  cudaGetSymbolAddress((void**)&dPROJ, PROJ);
    float* dCAT;   cudaGetSymbolAddress((void**)&dCAT, CATb);

    static int smem_set = 0;
    const int KATTN_SMEM = (16896 + 6656 + 1536 + 16) * 4;
    if (!smem_set) {
        cudaFuncSetAttribute(kattn, cudaFuncAttributeMaxDynamicSharedMemorySize, KATTN_SMEM);
        smem_set = 1;
    }

    kpack<<<1728, 256>>>(wq, wk, wv, wqp, wkp, wvp);
    {   // PROJ = s_i @ WPROJ : 1024 x 1152 x 384
        dim3 g(1152 / 64, 1024 / 64);
        sgemm_k<<<g, 256>>>(s_i, dWPROJ, dPROJ, 1024, 1152, 384, nullptr);
    }
    ktransform<<<1024, 32>>>(rots, trans, gamma);
    {
        dim3 g(8, 8, 24);
        kscore<<<g, 256>>>();
    }
    kattn<<<1024, 512, KATTN_SMEM>>>(z_ij, wb);
    {
        dim3 g(8, 24);
        kagg<<<g, 256>>>();
    }
    kepi<<<1024, 96>>>(rots, trans);
    {   // out = CAT @ wout + bout : 1024 x 384 x 2112
        dim3 g(384 / 64, 1024 / 64);
        sgemm_k<<<g, 256>>>(dCAT, wout, out, 1024, 384, 2112, bout);
    }
}

// round 6
// speedup vs baseline: 1.9287x; 1.1246x over previous
#include <cuda_runtime.h>
#include <math.h>

// B=2 N=512 CS=384 CZ=128 H=12 D=16 P=4 PV=8
// PROJ cols: q 0..191 | k 192..383 | v 384..575 | qp 576..719 | kp 720..863 | vp 864..1151
// CAT=2112: o_hat 0..1535 | o 1536..1727 | o_hp 1728..2015 | norm 2016..2111

__device__ float WPROJ[384 * 1152];
__device__ float PROJ[1024 * 1152];
__device__ float QQb[1024 * 384];
__device__ float KKb[1024 * 384];
__device__ float TVb[1024 * 288];
__device__ float CATb[1024 * 2112];
__device__ float SCA[2 * 12 * 512 * 512];   // scores, then normalized attention (in-place)
__device__ float OHP[1024 * 288];           // global-frame point aggregation
__device__ float OUTPART[4 * 1024 * 384];   // split-K partials for output GEMM

// ---------------- K1: pack projection weights ----------------
__global__ void kpack(const float* __restrict__ wq, const float* __restrict__ wk,
                      const float* __restrict__ wv, const float* __restrict__ wqp,
                      const float* __restrict__ wkp, const float* __restrict__ wvp) {
    int e = blockIdx.x * 256 + threadIdx.x;  // 1728*256 = 442368 = 384*1152
    int c = e / 1152, col = e - c * 1152;
    float v;
    if (col < 192)       v = wq[c * 192 + col];
    else if (col < 384)  v = wk[c * 192 + col - 192];
    else if (col < 576)  v = wv[c * 192 + col - 384];
    else if (col < 720)  v = wqp[c * 144 + col - 576];
    else if (col < 864)  v = wkp[c * 144 + col - 720];
    else                 v = wvp[c * 288 + col - 864];
    WPROJ[e] = v;
}

// ---------------- tiled SGEMM 64x64x16, optional split-K ----------------
__global__ __launch_bounds__(256)
void sgemm_k(const float* __restrict__ A, const float* __restrict__ Bm,
             float* __restrict__ C, int M, int Nn, int K, int Ksl,
             const float* __restrict__ bias) {
    const int BK = 16;
    __shared__ float As[BK][64];
    __shared__ float Bs[BK][64];
    int t = threadIdx.x;
    int tx = t % 16, ty = t / 16;
    int row0 = blockIdx.y * 64, col0 = blockIdx.x * 64;
    int kbeg = blockIdx.z * Ksl, kend = kbeg + Ksl;
    float* Cp = C + (size_t)blockIdx.z * M * Nn;
    float acc[4][4] = {};
    for (int k0 = kbeg; k0 < kend; k0 += BK) {
        __syncthreads();
        {
            int r = t / 4, kk = (t % 4) * 4;
            float4 v = *(const float4*)(A + (size_t)(row0 + r) * K + k0 + kk);
            As[kk][r] = v.x; As[kk + 1][r] = v.y; As[kk + 2][r] = v.z; As[kk + 3][r] = v.w;
        }
        {
            int kk = t / 16, n4 = (t % 16) * 4;
            *(float4*)(&Bs[kk][n4]) = *(const float4*)(Bm + (size_t)(k0 + kk) * Nn + col0 + n4);
        }
        __syncthreads();
#pragma unroll
        for (int kk = 0; kk < BK; kk++) {
            float4 ra = *(const float4*)(&As[kk][ty * 4]);
            float4 rb = *(const float4*)(&Bs[kk][tx * 4]);
            acc[0][0] += ra.x * rb.x; acc[0][1] += ra.x * rb.y; acc[0][2] += ra.x * rb.z; acc[0][3] += ra.x * rb.w;
            acc[1][0] += ra.y * rb.x; acc[1][1] += ra.y * rb.y; acc[1][2] += ra.y * rb.z; acc[1][3] += ra.y * rb.w;
            acc[2][0] += ra.z * rb.x; acc[2][1] += ra.z * rb.y; acc[2][2] += ra.z * rb.z; acc[2][3] += ra.z * rb.w;
            acc[3][0] += ra.w * rb.x; acc[3][1] += ra.w * rb.y; acc[3][2] += ra.w * rb.z; acc[3][3] += ra.w * rb.w;
        }
    }
#pragma unroll
    for (int u = 0; u < 4; u++) {
        int r = row0 + ty * 4 + u;
        float4 o = make_float4(acc[u][0], acc[u][1], acc[u][2], acc[u][3]);
        if (bias) {
            const float4 bb = *(const float4*)(bias + col0 + tx * 4);
            o.x += bb.x; o.y += bb.y; o.z += bb.z; o.w += bb.w;
        }
        *(float4*)(Cp + (size_t)r * Nn + col0 + tx * 4) = o;
    }
}

// ---------------- reduce split-K partials + bias ----------------
__global__ void kreduce(float* __restrict__ out, const float* __restrict__ bout) {
    int e = blockIdx.x * 256 + threadIdx.x;   // 393216 total
    const int PL = 1024 * 384;
    float s = OUTPART[e] + OUTPART[PL + e] + OUTPART[2 * PL + e] + OUTPART[3 * PL + e];
    out[e] = s + bout[e % 384];
}

// ---------------- K3: rigid transforms + QQ/KK/TV packing ----------------
__global__ void ktransform(const float* __restrict__ rots, const float* __restrict__ trans,
                           const float* __restrict__ gamma) {
    int row = blockIdx.x;
    int h = threadIdx.x;
    if (h >= 12) return;
    const float* pr = PROJ + (size_t)row * 1152;
    float R0 = rots[row * 9 + 0], R1 = rots[row * 9 + 1], R2 = rots[row * 9 + 2];
    float R3 = rots[row * 9 + 3], R4 = rots[row * 9 + 4], R5 = rots[row * 9 + 5];
    float R6 = rots[row * 9 + 6], R7 = rots[row * 9 + 7], R8 = rots[row * 9 + 8];
    float t0 = trans[row * 3 + 0], t1 = trans[row * 3 + 1], t2 = trans[row * 3 + 2];
    float* QQ = QQb + (size_t)row * 384 + h * 32;
    float* KK = KKb + (size_t)row * 384 + h * 32;
    float cg = 0.11785113019775793f * gamma[h];  // 0.5 * sqrt(2/36) * gamma
#pragma unroll
    for (int d = 0; d < 16; d++) {
        QQ[d] = pr[h * 16 + d] * 0.25f;          // fold 1/sqrt(D)
        KK[d] = pr[192 + h * 16 + d];
    }
    float sq2 = 0.f, sk2 = 0.f;
#pragma unroll
    for (int p = 0; p < 4; p++) {
        const float* qp = pr + 576 + h * 12 + p * 3;
        float x = qp[0], y = qp[1], zz = qp[2];
        float gx = R0 * x + R1 * y + R2 * zz + t0;
        float gy = R3 * x + R4 * y + R5 * zz + t1;
        float gz = R6 * x + R7 * y + R8 * zz + t2;
        QQ[16 + p * 3 + 0] = 2.f * cg * gx;
        QQ[16 + p * 3 + 1] = 2.f * cg * gy;
        QQ[16 + p * 3 + 2] = 2.f * cg * gz;
        sq2 += gx * gx + gy * gy + gz * gz;
        const float* kp = pr + 720 + h * 12 + p * 3;
        x = kp[0]; y = kp[1]; zz = kp[2];
        gx = R0 * x + R1 * y + R2 * zz + t0;
        gy = R3 * x + R4 * y + R5 * zz + t1;
        gz = R6 * x + R7 * y + R8 * zz + t2;
        KK[16 + p * 3 + 0] = gx; KK[16 + p * 3 + 1] = gy; KK[16 + p * 3 + 2] = gz;
        sk2 += gx * gx + gy * gy + gz * gz;
    }
    QQ[28] = -cg;       KK[28] = sk2;
    QQ[29] = -cg * sq2; KK[29] = 1.f;
    QQ[30] = 0.f; QQ[31] = 0.f; KK[30] = 0.f; KK[31] = 0.f;
    float* tp = TVb + (size_t)row * 288 + h * 24;
#pragma unroll
    for (int p = 0; p < 8; p++) {
        const float* vp = pr + 864 + h * 24 + p * 3;
        float x = vp[0], y = vp[1], zz = vp[2];
        tp[p * 3 + 0] = R0 * x + R1 * y + R2 * zz + t0;
        tp[p * 3 + 1] = R3 * x + R4 * y + R5 * zz + t1;
        tp[p * 3 + 2] = R6 * x + R7 * y + R8 * zz + t2;
    }
}

// ---------------- K4: score GEMM  SC[bh][i][j] = QQ[i,h,:].KK[j,h,:] (K=32) ----------------
__global__ __launch_bounds__(256) void kscore() {
    __shared__ float As[32][68];
    __shared__ float Bs[32][68];
    int t = threadIdx.x;
    int bh = blockIdx.z, b = bh / 12, h = bh % 12;
    int i0 = blockIdx.y * 64, j0 = blockIdx.x * 64;
#pragma unroll
    for (int s = 0; s < 2; s++) {
        int idx = t + s * 256;
        int r = idx >> 3, c4 = (idx & 7) * 4;
        float4 va = *(const float4*)(QQb + (size_t)(b * 512 + i0 + r) * 384 + h * 32 + c4);
        As[c4][r] = va.x; As[c4 + 1][r] = va.y; As[c4 + 2][r] = va.z; As[c4 + 3][r] = va.w;
        float4 vb = *(const float4*)(KKb + (size_t)(b * 512 + j0 + r) * 384 + h * 32 + c4);
        Bs[c4][r] = vb.x; Bs[c4 + 1][r] = vb.y; Bs[c4 + 2][r] = vb.z; Bs[c4 + 3][r] = vb.w;
    }
    __syncthreads();
    int tx = t & 15, ty = t >> 4;
    float acc[4][4] = {};
#pragma unroll
    for (int kk = 0; kk < 32; kk++) {
        float4 ra = *(const float4*)(&As[kk][ty * 4]);
        float4 rb = *(const float4*)(&Bs[kk][tx * 4]);
        acc[0][0] += ra.x * rb.x; acc[0][1] += ra.x * rb.y; acc[0][2] += ra.x * rb.z; acc[0][3] += ra.x * rb.w;
        acc[1][0] += ra.y * rb.x; acc[1][1] += ra.y * rb.y; acc[1][2] += ra.y * rb.z; acc[1][3] += ra.y * rb.w;
        acc[2][0] += ra.z * rb.x; acc[2][1] += ra.z * rb.y; acc[2][2] += ra.z * rb.z; acc[2][3] += ra.z * rb.w;
        acc[3][0] += ra.w * rb.x; acc[3][1] += ra.w * rb.y; acc[3][2] += ra.w * rb.z; acc[3][3] += ra.w * rb.w;
    }
#pragma unroll
    for (int u = 0; u < 4; u++) {
        float4 o = make_float4(acc[u][0], acc[u][1], acc[u][2], acc[u][3]);
        *(float4*)(SCA + ((size_t)bh * 512 + i0 + ty * 4 + u) * 512 + j0 + tx * 4) = o;
    }
}

// ---------------- K5: fused attention per (b,i) ----------------
// dyn smem: zs 128*132 | lg 512*16 | wbT 12*128 | rinv 16   (~106.6 KB)
__global__ __launch_bounds__(512)
void kattn(const float* __restrict__ z, const float* __restrict__ wb) {
    extern __shared__ float sm[];
    float* zs = sm;                    // 16896 floats (reused as "part", pitch 16)
    float* lg = sm + 16896;            // 8192 (512 x pitch16)
    float* wbT = sm + 25088;           // 1536
    float* rinv = sm + 26624;          // 16
    int t = threadIdx.x;
    int row = blockIdx.x, b = row >> 9, i = row & 511;
    const float* zrow = z + (size_t)row * 65536;

    for (int e = t; e < 1536; e += 512) {
        int h = e >> 7, c = e & 127;
        wbT[e] = wb[c * 12 + h];
    }

    int jl = t & 127, g = t >> 7;
    const float4* w0 = (const float4*)(wbT + g * 128);
    const float4* w1 = (const float4*)(wbT + (g + 4) * 128);
    const float4* w2 = (const float4*)(wbT + (g + 8) * 128);

    // ---- Pass 1: bias GEMV from smem-staged z + precomputed score ----
    for (int tile = 0; tile < 4; tile++) {
        __syncthreads();
#pragma unroll
        for (int s = 0; s < 8; s++) {
            int idx = t + s * 512;
            int r = idx >> 5, c4 = idx & 31;
            float4 v = *(const float4*)(zrow + (size_t)(tile * 128 + r) * 128 + c4 * 4);
            *(float4*)(zs + r * 132 + c4 * 4) = v;
        }
        __syncthreads();
        float a0 = 0.f, a1 = 0.f, a2 = 0.f;
        const float4* zv4 = (const float4*)(zs + jl * 132);
#pragma unroll
        for (int c4 = 0; c4 < 32; c4++) {
            float4 zq = zv4[c4];
            float4 x0 = w0[c4], x1 = w1[c4], x2 = w2[c4];
            a0 += zq.x * x0.x + zq.y * x0.y + zq.z * x0.z + zq.w * x0.w;
            a1 += zq.x * x1.x + zq.y * x1.y + zq.z * x1.z + zq.w * x1.w;
            a2 += zq.x * x2.x + zq.y * x2.y + zq.z * x2.z + zq.w * x2.w;
        }
        int j = tile * 128 + jl;
        size_t pl = (size_t)512 * 512;
        size_t base = ((size_t)(b * 12) * 512 + i) * 512 + j;
        float s0 = SCA[base + (size_t)g * pl];
        float s1 = SCA[base + (size_t)(g + 4) * pl];
        float s2 = SCA[base + (size_t)(g + 8) * pl];
        const float WL = 0.5773502691896258f;
        lg[j * 16 + g]     = WL * (a0 + s0);
        lg[j * 16 + g + 4] = WL * (a1 + s1);
        lg[j * 16 + g + 8] = WL * (a2 + s2);
    }
    __syncthreads();

    // ---- Softmax: warp w handles head w ----
    {
        int w = t >> 5, l = t & 31;
        if (w < 12) {
            float m = -1e30f;
            for (int jj = l; jj < 512; jj += 32) m = fmaxf(m, lg[jj * 16 + w]);
#pragma unroll
            for (int o = 16; o; o >>= 1) m = fmaxf(m, __shfl_xor_sync(0xffffffffu, m, o));
            float s = 0.f;
            for (int jj = l; jj < 512; jj += 32) {
                float e = __expf(lg[jj * 16 + w] - m);
                lg[jj * 16 + w] = e;
                s += e;
            }
#pragma unroll
            for (int o = 16; o; o >>= 1) s += __shfl_xor_sync(0xffffffffu, s, o);
            if (l == 0) rinv[w] = 1.f / s;
        }
    }
    __syncthreads();

    // ---- Write normalized attention planes (in-place over SC) ----
    {
        int j = t;
        size_t pl = (size_t)512 * 512;
        size_t base = ((size_t)(b * 12) * 512 + i) * 512 + j;
#pragma unroll
        for (int h = 0; h < 12; h++)
            SCA[base + (size_t)h * pl] = lg[j * 16 + h] * rinv[h];
    }

    // ---- Pass 2: o_hat = sum_j a*z, j-quartered, float4 lg reads ----
    int d = t & 127, jq = t >> 7;
    float acc[12] = {};
    const float* zc = zrow + (size_t)jq * 16384 + d;
    const float4* lgp = (const float4*)(lg + (size_t)jq * 128 * 16);
#pragma unroll 4
    for (int jj = 0; jj < 128; jj++) {
        float zv = __ldg(zc + jj * 128);
        float4 a0 = lgp[jj * 4], a1 = lgp[jj * 4 + 1], a2 = lgp[jj * 4 + 2];
        acc[0] += a0.x * zv; acc[1] += a0.y * zv; acc[2] += a0.z * zv; acc[3] += a0.w * zv;
        acc[4] += a1.x * zv; acc[5] += a1.y * zv; acc[6] += a1.z * zv; acc[7] += a1.w * zv;
        acc[8] += a2.x * zv; acc[9] += a2.y * zv; acc[10] += a2.z * zv; acc[11] += a2.w * zv;
    }
    __syncthreads();   // zs free -> reuse as partials, pitch 16
    float* part = zs;
#pragma unroll
    for (int u = 0; u < 3; u++)
        *(float4*)(part + (jq * 128 + d) * 16 + u * 4) =
            make_float4(acc[u * 4], acc[u * 4 + 1], acc[u * 4 + 2], acc[u * 4 + 3]);
    __syncthreads();
    float* cat = CATb + (size_t)row * 2112;
#pragma unroll
    for (int u = 0; u < 3; u++) {
        int e = t + u * 512;
        int h = e >> 7, dd = e & 127;
        float s = part[dd * 16 + h] + part[(128 + dd) * 16 + h] +
                  part[(256 + dd) * 16 + h] + part[(384 + dd) * 16 + h];
        cat[h * 128 + dd] = s * rinv[h];
    }
}

// ---------------- K6: value aggregation GEMMs  A[bh] x [v|tv] ----------------
__global__ __launch_bounds__(256) void kagg() {
    __shared__ float As[64 * 68];   // [i][j], pitch 68
    __shared__ float Bs[64 * 41];   // [j][c], c<16 -> v, else tv
    int t = threadIdx.x;
    int bh = blockIdx.y, b = bh / 12, h = bh % 12;
    int i0 = blockIdx.x * 64;
    int il = t & 63, cp = t >> 6;
    float acc[10] = {};
    for (int jt = 0; jt < 8; jt++) {
        __syncthreads();
#pragma unroll
        for (int s = 0; s < 4; s++) {
            int idx = t + s * 256;
            int r = idx >> 4, j4 = (idx & 15) * 4;
            float4 v = *(const float4*)(SCA + ((size_t)bh * 512 + i0 + r) * 512 + jt * 64 + j4);
            *(float4*)(As + r * 68 + j4) = v;
        }
#pragma unroll
        for (int s = 0; s < 10; s++) {
            int idx = t + s * 256;
            int jj = idx / 40, c = idx - jj * 40;
            int jg = b * 512 + jt * 64 + jj;
            float v = (c < 16) ? PROJ[(size_t)jg * 1152 + 384 + h * 16 + c]
                               : TVb[(size_t)jg * 288 + h * 24 + (c - 16)];
            Bs[jj * 41 + c] = v;
        }
        __syncthreads();
        const float4* a4 = (const float4*)(As + il * 68);
#pragma unroll
        for (int j4 = 0; j4 < 16; j4++) {
            float4 av = a4[j4];
#pragma unroll
            for (int u = 0; u < 4; u++) {
                float a = u == 0 ? av.x : u == 1 ? av.y : u == 2 ? av.z : av.w;
                const float* brow = Bs + (j4 * 4 + u) * 41 + cp;
#pragma unroll
                for (int cc = 0; cc < 10; cc++) acc[cc] += a * brow[cc * 4];
            }
        }
    }
    size_t crow = (size_t)(b * 512 + i0 + il);
#pragma unroll
    for (int cc = 0; cc < 10; cc++) {
        int col = cp + cc * 4;
        if (col < 16) CATb[crow * 2112 + 1536 + h * 16 + col] = acc[cc];
        else          OHP[crow * 288 + h * 24 + (col - 16)] = acc[cc];
    }
}

// ---------------- K7: rigid invert + norms ----------------
__global__ void kepi(const float* __restrict__ rots, const float* __restrict__ trans) {
    __shared__ float R[9], T[3];
    int row = blockIdx.x, t = threadIdx.x;   // 96 threads
    if (t < 9) R[t] = rots[row * 9 + t];
    if (t < 3) T[t] = trans[row * 3 + t];
    __syncthreads();
    size_t base = (size_t)row * 288 + t * 3;
    float gx = OHP[base + 0] - T[0];
    float gy = OHP[base + 1] - T[1];
    float gz = OHP[base + 2] - T[2];
    float lx = R[0] * gx + R[3] * gy + R[6] * gz;
    float ly = R[1] * gx + R[4] * gy + R[7] * gz;
    float lz = R[2] * gx + R[5] * gy + R[8] * gz;
    float* cat = CATb + (size_t)row * 2112;
    cat[1728 + t * 3 + 0] = lx;
    cat[1728 + t * 3 + 1] = ly;
    cat[1728 + t * 3 + 2] = lz;
    cat[2016 + t] = sqrtf(lx * lx + ly * ly + lz * lz);
}

extern "C" void kernel_launch(void* const* d_in, const int* in_sizes, int n_in,
                              void* d_out, int out_size) {
    const float* s_i   = (const float*)d_in[0];
    const float* z_ij  = (const float*)d_in[1];
    const float* rots  = (const float*)d_in[2];
    const float* trans = (const float*)d_in[3];
    const float* wq    = (const float*)d_in[4];
    const float* wk    = (const float*)d_in[5];
    const float* wv    = (const float*)d_in[6];
    const float* wqp   = (const float*)d_in[7];
    const float* wkp   = (const float*)d_in[8];
    const float* wvp   = (const float*)d_in[9];
    const float* wb    = (const float*)d_in[10];
    const float* gamma = (const float*)d_in[11];
    const float* wout  = (const float*)d_in[12];
    const float* bout  = (const float*)d_in[13];
    float* out = (float*)d_out;

    float* dWPROJ; cudaGetSymbolAddress((void**)&dWPROJ, WPROJ);
    float* dPROJ;  cudaGetSymbolAddress((void**)&dPROJ, PROJ);
    float* dCAT;   cudaGetSymbolAddress((void**)&dCAT, CATb);
    float* dOUTP;  cudaGetSymbolAddress((void**)&dOUTP, OUTPART);

    static int smem_set = 0;
    const int KATTN_SMEM = (16896 + 8192 + 1536 + 16) * 4;
    if (!smem_set) {
        cudaFuncSetAttribute(kattn, cudaFuncAttributeMaxDynamicSharedMemorySize, KATTN_SMEM);
        smem_set = 1;
    }

    kpack<<<1728, 256>>>(wq, wk, wv, wqp, wkp, wvp);
    {   // PROJ = s_i @ WPROJ : 1024 x 1152 x 384
        dim3 g(1152 / 64, 1024 / 64, 1);
        sgemm_k<<<g, 256>>>(s_i, dWPROJ, dPROJ, 1024, 1152, 384, 384, nullptr);
    }
    ktransform<<<1024, 32>>>(rots, trans, gamma);
    {
        dim3 g(8, 8, 24);
        kscore<<<g, 256>>>();
    }
    kattn<<<1024, 512, KATTN_SMEM>>>(z_ij, wb);
    {
        dim3 g(8, 24);
        kagg<<<g, 256>>>();
    }
    kepi<<<1024, 96>>>(rots, trans);
    {   // OUTPART[s] = CAT @ wout over K-slice s : 1024 x 384 x (4 x 528)
        dim3 g(384 / 64, 1024 / 64, 4);
        sgemm_k<<<g, 256>>>(dCAT, wout, dOUTP, 1024, 384, 2112, 528, nullptr);
    }
    kreduce<<<1536, 256>>>(out, bout);
}

// round 7
// speedup vs baseline: 2.1437x; 1.1115x over previous
#include <cuda_runtime.h>
#include <math.h>

// B=2 N=512 CS=384 CZ=128 H=12 D=16 P=4 PV=8
// PROJ cols: q 0..191 | k 192..383 | v 384..575 | qp 576..719 | kp 720..863 | vp 864..1151
// CAT=2112: o_hat 0..1535 | o 1536..1727 | o_hp 1728..2015 | norm 2016..2111

__device__ float WPROJ[384 * 1152];
__device__ float PROJ[1024 * 1152];
__device__ float QQb[1024 * 384];
__device__ float KKb[1024 * 384];
__device__ float TVb[1024 * 288];
__device__ float CATb[1024 * 2112];
__device__ float SCA[2 * 12 * 512 * 512];   // scores, then normalized attention (in-place)
__device__ float SMAXb[24 * 512];           // per (b,h,i): W_L * max_j score
__device__ float OHP[1024 * 288];           // global-frame point aggregation
__device__ float OUTPART[4 * 1024 * 384];   // split-K partials for output GEMM

// ---------------- K1: pack projection weights ----------------
__global__ void kpack(const float* __restrict__ wq, const float* __restrict__ wk,
                      const float* __restrict__ wv, const float* __restrict__ wqp,
                      const float* __restrict__ wkp, const float* __restrict__ wvp) {
    int e = blockIdx.x * 256 + threadIdx.x;  // 1728*256 = 442368 = 384*1152
    int c = e / 1152, col = e - c * 1152;
    float v;
    if (col < 192)       v = wq[c * 192 + col];
    else if (col < 384)  v = wk[c * 192 + col - 192];
    else if (col < 576)  v = wv[c * 192 + col - 384];
    else if (col < 720)  v = wqp[c * 144 + col - 576];
    else if (col < 864)  v = wkp[c * 144 + col - 720];
    else                 v = wvp[c * 288 + col - 864];
    WPROJ[e] = v;
}

// ---------------- tiled SGEMM 64x64x16, optional split-K ----------------
__global__ __launch_bounds__(256)
void sgemm_k(const float* __restrict__ A, const float* __restrict__ Bm,
             float* __restrict__ C, int M, int Nn, int K, int Ksl,
             const float* __restrict__ bias) {
    const int BK = 16;
    __shared__ float As[BK][64];
    __shared__ float Bs[BK][64];
    int t = threadIdx.x;
    int tx = t % 16, ty = t / 16;
    int row0 = blockIdx.y * 64, col0 = blockIdx.x * 64;
    int kbeg = blockIdx.z * Ksl, kend = kbeg + Ksl;
    float* Cp = C + (size_t)blockIdx.z * M * Nn;
    float acc[4][4] = {};
    for (int k0 = kbeg; k0 < kend; k0 += BK) {
        __syncthreads();
        {
            int r = t / 4, kk = (t % 4) * 4;
            float4 v = *(const float4*)(A + (size_t)(row0 + r) * K + k0 + kk);
            As[kk][r] = v.x; As[kk + 1][r] = v.y; As[kk + 2][r] = v.z; As[kk + 3][r] = v.w;
        }
        {
            int kk = t / 16, n4 = (t % 16) * 4;
            *(float4*)(&Bs[kk][n4]) = *(const float4*)(Bm + (size_t)(k0 + kk) * Nn + col0 + n4);
        }
        __syncthreads();
#pragma unroll
        for (int kk = 0; kk < BK; kk++) {
            float4 ra = *(const float4*)(&As[kk][ty * 4]);
            float4 rb = *(const float4*)(&Bs[kk][tx * 4]);
            acc[0][0] += ra.x * rb.x; acc[0][1] += ra.x * rb.y; acc[0][2] += ra.x * rb.z; acc[0][3] += ra.x * rb.w;
            acc[1][0] += ra.y * rb.x; acc[1][1] += ra.y * rb.y; acc[1][2] += ra.y * rb.z; acc[1][3] += ra.y * rb.w;
            acc[2][0] += ra.z * rb.x; acc[2][1] += ra.z * rb.y; acc[2][2] += ra.z * rb.z; acc[2][3] += ra.z * rb.w;
            acc[3][0] += ra.w * rb.x; acc[3][1] += ra.w * rb.y; acc[3][2] += ra.w * rb.z; acc[3][3] += ra.w * rb.w;
        }
    }
#pragma unroll
    for (int u = 0; u < 4; u++) {
        int r = row0 + ty * 4 + u;
        float4 o = make_float4(acc[u][0], acc[u][1], acc[u][2], acc[u][3]);
        if (bias) {
            const float4 bb = *(const float4*)(bias + col0 + tx * 4);
            o.x += bb.x; o.y += bb.y; o.z += bb.z; o.w += bb.w;
        }
        *(float4*)(Cp + (size_t)r * Nn + col0 + tx * 4) = o;
    }
}

// ---------------- reduce split-K partials + bias ----------------
__global__ void kreduce(float* __restrict__ out, const float* __restrict__ bout) {
    int e = blockIdx.x * 256 + threadIdx.x;   // 393216 total
    const int PL = 1024 * 384;
    float s = OUTPART[e] + OUTPART[PL + e] + OUTPART[2 * PL + e] + OUTPART[3 * PL + e];
    out[e] = s + bout[e % 384];
}

// ---------------- K3: rigid transforms + QQ/KK/TV packing ----------------
__global__ void ktransform(const float* __restrict__ rots, const float* __restrict__ trans,
                           const float* __restrict__ gamma) {
    int row = blockIdx.x;
    int h = threadIdx.x;
    if (h >= 12) return;
    const float* pr = PROJ + (size_t)row * 1152;
    float R0 = rots[row * 9 + 0], R1 = rots[row * 9 + 1], R2 = rots[row * 9 + 2];
    float R3 = rots[row * 9 + 3], R4 = rots[row * 9 + 4], R5 = rots[row * 9 + 5];
    float R6 = rots[row * 9 + 6], R7 = rots[row * 9 + 7], R8 = rots[row * 9 + 8];
    float t0 = trans[row * 3 + 0], t1 = trans[row * 3 + 1], t2 = trans[row * 3 + 2];
    float* QQ = QQb + (size_t)row * 384 + h * 32;
    float* KK = KKb + (size_t)row * 384 + h * 32;
    float cg = 0.11785113019775793f * gamma[h];  // 0.5 * sqrt(2/36) * gamma
#pragma unroll
    for (int d = 0; d < 16; d++) {
        QQ[d] = pr[h * 16 + d] * 0.25f;          // fold 1/sqrt(D)
        KK[d] = pr[192 + h * 16 + d];
    }
    float sq2 = 0.f, sk2 = 0.f;
#pragma unroll
    for (int p = 0; p < 4; p++) {
        const float* qp = pr + 576 + h * 12 + p * 3;
        float x = qp[0], y = qp[1], zz = qp[2];
        float gx = R0 * x + R1 * y + R2 * zz + t0;
        float gy = R3 * x + R4 * y + R5 * zz + t1;
        float gz = R6 * x + R7 * y + R8 * zz + t2;
        QQ[16 + p * 3 + 0] = 2.f * cg * gx;
        QQ[16 + p * 3 + 1] = 2.f * cg * gy;
        QQ[16 + p * 3 + 2] = 2.f * cg * gz;
        sq2 += gx * gx + gy * gy + gz * gz;
        const float* kp = pr + 720 + h * 12 + p * 3;
        x = kp[0]; y = kp[1]; zz = kp[2];
        gx = R0 * x + R1 * y + R2 * zz + t0;
        gy = R3 * x + R4 * y + R5 * zz + t1;
        gz = R6 * x + R7 * y + R8 * zz + t2;
        KK[16 + p * 3 + 0] = gx; KK[16 + p * 3 + 1] = gy; KK[16 + p * 3 + 2] = gz;
        sk2 += gx * gx + gy * gy + gz * gz;
    }
    QQ[28] = -cg;       KK[28] = sk2;
    QQ[29] = -cg * sq2; KK[29] = 1.f;
    QQ[30] = 0.f; QQ[31] = 0.f; KK[30] = 0.f; KK[31] = 0.f;
    float* tp = TVb + (size_t)row * 288 + h * 24;
#pragma unroll
    for (int p = 0; p < 8; p++) {
        const float* vp = pr + 864 + h * 24 + p * 3;
        float x = vp[0], y = vp[1], zz = vp[2];
        tp[p * 3 + 0] = R0 * x + R1 * y + R2 * zz + t0;
        tp[p * 3 + 1] = R3 * x + R4 * y + R5 * zz + t1;
        tp[p * 3 + 2] = R6 * x + R7 * y + R8 * zz + t2;
    }
}

// ---------------- K4: score GEMM  SC[bh][i][j] = QQ[i,h,:].KK[j,h,:] (K=32) ----------------
__global__ __launch_bounds__(256) void kscore() {
    __shared__ float As[32][68];
    __shared__ float Bs[32][68];
    int t = threadIdx.x;
    int bh = blockIdx.z, b = bh / 12, h = bh % 12;
    int i0 = blockIdx.y * 64, j0 = blockIdx.x * 64;
#pragma unroll
    for (int s = 0; s < 2; s++) {
        int idx = t + s * 256;
        int r = idx >> 3, c4 = (idx & 7) * 4;
        float4 va = *(const float4*)(QQb + (size_t)(b * 512 + i0 + r) * 384 + h * 32 + c4);
        As[c4][r] = va.x; As[c4 + 1][r] = va.y; As[c4 + 2][r] = va.z; As[c4 + 3][r] = va.w;
        float4 vb = *(const float4*)(KKb + (size_t)(b * 512 + j0 + r) * 384 + h * 32 + c4);
        Bs[c4][r] = vb.x; Bs[c4 + 1][r] = vb.y; Bs[c4 + 2][r] = vb.z; Bs[c4 + 3][r] = vb.w;
    }
    __syncthreads();
    int tx = t & 15, ty = t >> 4;
    float acc[4][4] = {};
#pragma unroll
    for (int kk = 0; kk < 32; kk++) {
        float4 ra = *(const float4*)(&As[kk][ty * 4]);
        float4 rb = *(const float4*)(&Bs[kk][tx * 4]);
        acc[0][0] += ra.x * rb.x; acc[0][1] += ra.x * rb.y; acc[0][2] += ra.x * rb.z; acc[0][3] += ra.x * rb.w;
        acc[1][0] += ra.y * rb.x; acc[1][1] += ra.y * rb.y; acc[1][2] += ra.y * rb.z; acc[1][3] += ra.y * rb.w;
        acc[2][0] += ra.z * rb.x; acc[2][1] += ra.z * rb.y; acc[2][2] += ra.z * rb.z; acc[2][3] += ra.z * rb.w;
        acc[3][0] += ra.w * rb.x; acc[3][1] += ra.w * rb.y; acc[3][2] += ra.w * rb.z; acc[3][3] += ra.w * rb.w;
    }
#pragma unroll
    for (int u = 0; u < 4; u++) {
        float4 o = make_float4(acc[u][0], acc[u][1], acc[u][2], acc[u][3]);
        *(float4*)(SCA + ((size_t)bh * 512 + i0 + ty * 4 + u) * 512 + j0 + tx * 4) = o;
    }
}

// ---------------- K4b: per-(b,h,i) score max (warp per row) ----------------
__global__ void kmax() {
    int w = (blockIdx.x * 256 + threadIdx.x) >> 5;   // row id, 12288 rows
    int l = threadIdx.x & 31;
    const float* p = SCA + (size_t)w * 512;
    float m = -1e30f;
#pragma unroll
    for (int k = 0; k < 16; k++) m = fmaxf(m, p[l + k * 32]);
#pragma unroll
    for (int o = 16; o; o >>= 1) m = fmaxf(m, __shfl_xor_sync(0xffffffffu, m, o));
    if (l == 0) SMAXb[w] = 0.5773502691896258f * m;
}

// ---------------- K5: single-pass fused attention per (b,i) ----------------
// dyn smem: zs 128*132 | lg 512*17 | wbT 12*128 | smaxs 12 | rinv 12 (+pad)
__global__ __launch_bounds__(512)
void kattn(const float* __restrict__ z, const float* __restrict__ wb) {
    extern __shared__ float sm[];
    float* zs = sm;                    // 16896 floats (reused as "part")
    float* lg = sm + 16896;            // 8704 (512 x pitch17), exp weights
    float* wbT = sm + 25600;           // 1536
    float* smaxs = sm + 27136;         // 12
    float* rinv = sm + 27152;          // 12 (+pad to 27168)
    int t = threadIdx.x;
    int row = blockIdx.x, b = row >> 9, i = row & 511;
    const float* zrow = z + (size_t)row * 65536;
    const size_t pl = (size_t)512 * 512;
    const size_t base = (size_t)(b * 12) * pl + (size_t)i * 512;

    for (int e = t; e < 1536; e += 512) {
        int h = e >> 7, c = e & 127;
        wbT[e] = wb[c * 12 + h];
    }
    if (t < 12) smaxs[t] = SMAXb[(size_t)(b * 12 + t) * 512 + i];

    int jl = t & 127, g = t >> 7;      // logit role
    const float4* w0 = (const float4*)(wbT + g * 128);
    const float4* w1 = (const float4*)(wbT + (g + 4) * 128);
    const float4* w2 = (const float4*)(wbT + (g + 8) * 128);
    int d4 = t & 31, g2 = (t >> 5) & 3, jq = t >> 7;   // agg role
    float acc[3][4] = {};              // heads {g2, g2+4, g2+8} x d = d4*4..+3

    for (int tile = 0; tile < 4; tile++) {
        __syncthreads();
#pragma unroll
        for (int s = 0; s < 8; s++) {
            int idx = t + s * 512;
            int r = idx >> 5, c4 = idx & 31;
            *(float4*)(zs + r * 132 + c4 * 4) =
                *(const float4*)(zrow + (size_t)(tile * 128 + r) * 128 + c4 * 4);
        }
        __syncthreads();
        // ---- logits + exp for j = tile*128 + jl (3 heads per thread) ----
        {
            float a0 = 0.f, a1 = 0.f, a2 = 0.f;
            const float4* zv4 = (const float4*)(zs + jl * 132);
#pragma unroll
            for (int c4 = 0; c4 < 32; c4++) {
                float4 zq = zv4[c4];
                float4 x0 = w0[c4], x1 = w1[c4], x2 = w2[c4];
                a0 += zq.x * x0.x + zq.y * x0.y + zq.z * x0.z + zq.w * x0.w;
                a1 += zq.x * x1.x + zq.y * x1.y + zq.z * x1.z + zq.w * x1.w;
                a2 += zq.x * x2.x + zq.y * x2.y + zq.z * x2.z + zq.w * x2.w;
            }
            int j = tile * 128 + jl;
            float s0 = SCA[base + (size_t)g * pl + j];
            float s1 = SCA[base + (size_t)(g + 4) * pl + j];
            float s2 = SCA[base + (size_t)(g + 8) * pl + j];
            const float WL = 0.5773502691896258f;
            lg[j * 17 + g]     = __expf(WL * (a0 + s0) - smaxs[g]);
            lg[j * 17 + g + 4] = __expf(WL * (a1 + s1) - smaxs[g + 4]);
            lg[j * 17 + g + 8] = __expf(WL * (a2 + s2) - smaxs[g + 8]);
        }
        __syncthreads();
        // ---- aggregate tile from smem: j-range [jq*32, jq*32+32) ----
        {
            const float* lgt = lg + (size_t)(tile * 128) * 17;
#pragma unroll 4
            for (int jj = 0; jj < 32; jj++) {
                int jjt = jq * 32 + jj;
                float4 zq = *(const float4*)(zs + jjt * 132 + d4 * 4);
                const float* wt = lgt + jjt * 17;
                float e0 = wt[g2], e1 = wt[g2 + 4], e2 = wt[g2 + 8];
                acc[0][0] += e0 * zq.x; acc[0][1] += e0 * zq.y; acc[0][2] += e0 * zq.z; acc[0][3] += e0 * zq.w;
                acc[1][0] += e1 * zq.x; acc[1][1] += e1 * zq.y; acc[1][2] += e1 * zq.z; acc[1][3] += e1 * zq.w;
                acc[2][0] += e2 * zq.x; acc[2][1] += e2 * zq.y; acc[2][2] += e2 * zq.z; acc[2][3] += e2 * zq.w;
            }
        }
    }
    __syncthreads();
    // ---- per-head sums -> rinv ----
    {
        int w = t >> 5, l = t & 31;
        if (w < 12) {
            float s = 0.f;
            for (int k = l; k < 512; k += 32) s += lg[k * 17 + w];
#pragma unroll
            for (int o = 16; o; o >>= 1) s += __shfl_xor_sync(0xffffffffu, s, o);
            if (l == 0) rinv[w] = 1.f / s;
        }
    }
    __syncthreads();
    // ---- write normalized attention planes for kagg ----
    {
        int j = t;
#pragma unroll
        for (int h = 0; h < 12; h++)
            SCA[base + (size_t)h * pl + j] = lg[j * 17 + h] * rinv[h];
    }
    // ---- combine j-quarter partials (reuse zs) ----
    float* part = zs;
#pragma unroll
    for (int c = 0; c < 4; c++) {
        int dd = jq * 128 + d4 * 4 + c;
        part[dd * 12 + g2]     = acc[0][c];
        part[dd * 12 + g2 + 4] = acc[1][c];
        part[dd * 12 + g2 + 8] = acc[2][c];
    }
    __syncthreads();
    float* cat = CATb + (size_t)row * 2112;
#pragma unroll
    for (int u = 0; u < 3; u++) {
        int e = t + u * 512;
        int d = e & 127, h = e >> 7;
        float s = part[d * 12 + h] + part[(128 + d) * 12 + h] +
                  part[(256 + d) * 12 + h] + part[(384 + d) * 12 + h];
        cat[h * 128 + d] = s * rinv[h];
    }
}

// ---------------- K6: value aggregation GEMMs  A[bh] x [v|tv] ----------------
__global__ __launch_bounds__(256) void kagg() {
    __shared__ float As[64 * 68];   // [i][j], pitch 68
    __shared__ float Bs[64 * 41];   // [j][c], c<16 -> v, else tv
    int t = threadIdx.x;
    int bh = blockIdx.y, b = bh / 12, h = bh % 12;
    int i0 = blockIdx.x * 64;
    int il = t & 63, cp = t >> 6;
    float acc[10] = {};
    for (int jt = 0; jt < 8; jt++) {
        __syncthreads();
#pragma unroll
        for (int s = 0; s < 4; s++) {
            int idx = t + s * 256;
            int r = idx >> 4, j4 = (idx & 15) * 4;
            float4 v = *(const float4*)(SCA + ((size_t)bh * 512 + i0 + r) * 512 + jt * 64 + j4);
            *(float4*)(As + r * 68 + j4) = v;
        }
#pragma unroll
        for (int s = 0; s < 10; s++) {
            int idx = t + s * 256;
            int jj = idx / 40, c = idx - jj * 40;
            int jg = b * 512 + jt * 64 + jj;
            float v = (c < 16) ? PROJ[(size_t)jg * 1152 + 384 + h * 16 + c]
                               : TVb[(size_t)jg * 288 + h * 24 + (c - 16)];
            Bs[jj * 41 + c] = v;
        }
        __syncthreads();
        const float4* a4 = (const float4*)(As + il * 68);
#pragma unroll
        for (int j4 = 0; j4 < 16; j4++) {
            float4 av = a4[j4];
#pragma unroll
            for (int u = 0; u < 4; u++) {
                float a = u == 0 ? av.x : u == 1 ? av.y : u == 2 ? av.z : av.w;
                const float* brow = Bs + (j4 * 4 + u) * 41 + cp;
#pragma unroll
                for (int cc = 0; cc < 10; cc++) acc[cc] += a * brow[cc * 4];
            }
        }
    }
    size_t crow = (size_t)(b * 512 + i0 + il);
#pragma unroll
    for (int cc = 0; cc < 10; cc++) {
        int col = cp + cc * 4;
        if (col < 16) CATb[crow * 2112 + 1536 + h * 16 + col] = acc[cc];
        else          OHP[crow * 288 + h * 24 + (col - 16)] = acc[cc];
    }
}

// ---------------- K7: rigid invert + norms ----------------
__global__ void kepi(const float* __restrict__ rots, const float* __restrict__ trans) {
    __shared__ float R[9], T[3];
    int row = blockIdx.x, t = threadIdx.x;   // 96 threads
    if (t < 9) R[t] = rots[row * 9 + t];
    if (t < 3) T[t] = trans[row * 3 + t];
    __syncthreads();
    size_t base = (size_t)row * 288 + t * 3;
    float gx = OHP[base + 0] - T[0];
    float gy = OHP[base + 1] - T[1];
    float gz = OHP[base + 2] - T[2];
    float lx = R[0] * gx + R[3] * gy + R[6] * gz;
    float ly = R[1] * gx + R[4] * gy + R[7] * gz;
    float lz = R[2] * gx + R[5] * gy + R[8] * gz;
    float* cat = CATb + (size_t)row * 2112;
    cat[1728 + t * 3 + 0] = lx;
    cat[1728 + t * 3 + 1] = ly;
    cat[1728 + t * 3 + 2] = lz;
    cat[2016 + t] = sqrtf(lx * lx + ly * ly + lz * lz);
}

extern "C" void kernel_launch(void* const* d_in, const int* in_sizes, int n_in,
                              void* d_out, int out_size) {
    const float* s_i   = (const float*)d_in[0];
    const float* z_ij  = (const float*)d_in[1];
    const float* rots  = (const float*)d_in[2];
    const float* trans = (const float*)d_in[3];
    const float* wq    = (const float*)d_in[4];
    const float* wk    = (const float*)d_in[5];
    const float* wv    = (const float*)d_in[6];
    const float* wqp   = (const float*)d_in[7];
    const float* wkp   = (const float*)d_in[8];
    const float* wvp   = (const float*)d_in[9];
    const float* wb    = (const float*)d_in[10];
    const float* gamma = (const float*)d_in[11];
    const float* wout  = (const float*)d_in[12];
    const float* bout  = (const float*)d_in[13];
    float* out = (float*)d_out;

    float* dWPROJ; cudaGetSymbolAddress((void**)&dWPROJ, WPROJ);
    float* dPROJ;  cudaGetSymbolAddress((void**)&dPROJ, PROJ);
    float* dCAT;   cudaGetSymbolAddress((void**)&dCAT, CATb);
    float* dOUTP;  cudaGetSymbolAddress((void**)&dOUTP, OUTPART);

    static int smem_set = 0;
    const int KATTN_SMEM = 27168 * 4;
    if (!smem_set) {
        cudaFuncSetAttribute(kattn, cudaFuncAttributeMaxDynamicSharedMemorySize, KATTN_SMEM);
        smem_set = 1;
    }

    kpack<<<1728, 256>>>(wq, wk, wv, wqp, wkp, wvp);
    {   // PROJ = s_i @ WPROJ : 1024 x 1152 x 384
        dim3 g(1152 / 64, 1024 / 64, 1);
        sgemm_k<<<g, 256>>>(s_i, dWPROJ, dPROJ, 1024, 1152, 384, 384, nullptr);
    }
    ktransform<<<1024, 32>>>(rots, trans, gamma);
    {
        dim3 g(8, 8, 24);
        kscore<<<g, 256>>>();
    }
    kmax<<<1536, 256>>>();
    kattn<<<1024, 512, KATTN_SMEM>>>(z_ij, wb);
    {
        dim3 g(8, 24);
        kagg<<<g, 256>>>();
    }
    kepi<<<1024, 96>>>(rots, trans);
    {   // OUTPART[s] = CAT @ wout over K-slice s : 1024 x 384 x (4 x 528)
        dim3 g(384 / 64, 1024 / 64, 4);
        sgemm_k<<<g, 256>>>(dCAT, wout, dOUTP, 1024, 384, 2112, 528, nullptr);
    }
    kreduce<<<1536, 256>>>(out, bout);
}

// round 8
// speedup vs baseline: 2.3270x; 1.0855x over previous
#include <cuda_runtime.h>
#include <math.h>

// B=2 N=512 CS=384 CZ=128 H=12 D=16 P=4 PV=8
// PROJ cols: q 0..191 | k 192..383 | v 384..575 | qp 576..719 | kp 720..863 | vp 864..1151
// CAT=2112: o_hat 0..1535 | o 1536..1727 | o_hp 1728..2015 | norm 2016..2111

__device__ float WPROJ[384 * 1152];
__device__ float PROJ[1024 * 1152];
__device__ float QQb[1024 * 384];
__device__ float KKb[1024 * 384];
__device__ float VTb[1024 * 480];           // per key row: 12h x [v(16) | tv(24)]
__device__ float CATb[1024 * 2112];
__device__ float SCA[2 * 12 * 512 * 512];   // scores, then unnormalized exp weights (in-place)
__device__ float SMAXPART[24 * 512 * 8];    // per (b,h,i): block maxes over 8 j-blocks
__device__ float RINVb[24 * 512];           // per (b,h,i): 1/sum(exp)
__device__ float OHP[1024 * 288];           // global-frame point aggregation
__device__ float OUTPART[4 * 1024 * 384];   // split-K partials for output GEMM

// ---------------- K1: pack projection weights ----------------
__global__ void kpack(const float* __restrict__ wq, const float* __restrict__ wk,
                      const float* __restrict__ wv, const float* __restrict__ wqp,
                      const float* __restrict__ wkp, const float* __restrict__ wvp) {
    int e = blockIdx.x * 256 + threadIdx.x;  // 1728*256 = 442368 = 384*1152
    int c = e / 1152, col = e - c * 1152;
    float v;
    if (col < 192)       v = wq[c * 192 + col];
    else if (col < 384)  v = wk[c * 192 + col - 192];
    else if (col < 576)  v = wv[c * 192 + col - 384];
    else if (col < 720)  v = wqp[c * 144 + col - 576];
    else if (col < 864)  v = wkp[c * 144 + col - 720];
    else                 v = wvp[c * 288 + col - 864];
    WPROJ[e] = v;
}

// ---------------- tiled SGEMM 64x64x16, optional split-K ----------------
__global__ __launch_bounds__(256)
void sgemm_k(const float* __restrict__ A, const float* __restrict__ Bm,
             float* __restrict__ C, int M, int Nn, int K, int Ksl,
             const float* __restrict__ bias) {
    const int BK = 16;
    __shared__ float As[BK][64];
    __shared__ float Bs[BK][64];
    int t = threadIdx.x;
    int tx = t % 16, ty = t / 16;
    int row0 = blockIdx.y * 64, col0 = blockIdx.x * 64;
    int kbeg = blockIdx.z * Ksl, kend = kbeg + Ksl;
    float* Cp = C + (size_t)blockIdx.z * M * Nn;
    float acc[4][4] = {};
    for (int k0 = kbeg; k0 < kend; k0 += BK) {
        __syncthreads();
        {
            int r = t / 4, kk = (t % 4) * 4;
            float4 v = *(const float4*)(A + (size_t)(row0 + r) * K + k0 + kk);
            As[kk][r] = v.x; As[kk + 1][r] = v.y; As[kk + 2][r] = v.z; As[kk + 3][r] = v.w;
        }
        {
            int kk = t / 16, n4 = (t % 16) * 4;
            *(float4*)(&Bs[kk][n4]) = *(const float4*)(Bm + (size_t)(k0 + kk) * Nn + col0 + n4);
        }
        __syncthreads();
#pragma unroll
        for (int kk = 0; kk < BK; kk++) {
            float4 ra = *(const float4*)(&As[kk][ty * 4]);
            float4 rb = *(const float4*)(&Bs[kk][tx * 4]);
            acc[0][0] += ra.x * rb.x; acc[0][1] += ra.x * rb.y; acc[0][2] += ra.x * rb.z; acc[0][3] += ra.x * rb.w;
            acc[1][0] += ra.y * rb.x; acc[1][1] += ra.y * rb.y; acc[1][2] += ra.y * rb.z; acc[1][3] += ra.y * rb.w;
            acc[2][0] += ra.z * rb.x; acc[2][1] += ra.z * rb.y; acc[2][2] += ra.z * rb.z; acc[2][3] += ra.z * rb.w;
            acc[3][0] += ra.w * rb.x; acc[3][1] += ra.w * rb.y; acc[3][2] += ra.w * rb.z; acc[3][3] += ra.w * rb.w;
        }
    }
#pragma unroll
    for (int u = 0; u < 4; u++) {
        int r = row0 + ty * 4 + u;
        float4 o = make_float4(acc[u][0], acc[u][1], acc[u][2], acc[u][3]);
        if (bias) {
            const float4 bb = *(const float4*)(bias + col0 + tx * 4);
            o.x += bb.x; o.y += bb.y; o.z += bb.z; o.w += bb.w;
        }
        *(float4*)(Cp + (size_t)r * Nn + col0 + tx * 4) = o;
    }
}

// ---------------- reduce split-K partials + bias ----------------
__global__ void kreduce(float* __restrict__ out, const float* __restrict__ bout) {
    int e = blockIdx.x * 256 + threadIdx.x;   // 393216 total
    const int PL = 1024 * 384;
    float s = OUTPART[e] + OUTPART[PL + e] + OUTPART[2 * PL + e] + OUTPART[3 * PL + e];
    out[e] = s + bout[e % 384];
}

// ---------------- K3: rigid transforms + QQ/KK/VT packing ----------------
__global__ void ktransform(const float* __restrict__ rots, const float* __restrict__ trans,
                           const float* __restrict__ gamma) {
    int row = blockIdx.x;
    int h = threadIdx.x;
    if (h >= 12) return;
    const float* pr = PROJ + (size_t)row * 1152;
    float R0 = rots[row * 9 + 0], R1 = rots[row * 9 + 1], R2 = rots[row * 9 + 2];
    float R3 = rots[row * 9 + 3], R4 = rots[row * 9 + 4], R5 = rots[row * 9 + 5];
    float R6 = rots[row * 9 + 6], R7 = rots[row * 9 + 7], R8 = rots[row * 9 + 8];
    float t0 = trans[row * 3 + 0], t1 = trans[row * 3 + 1], t2 = trans[row * 3 + 2];
    float* QQ = QQb + (size_t)row * 384 + h * 32;
    float* KK = KKb + (size_t)row * 384 + h * 32;
    float cg = 0.11785113019775793f * gamma[h];  // 0.5 * sqrt(2/36) * gamma
#pragma unroll
    for (int d = 0; d < 16; d++) {
        QQ[d] = pr[h * 16 + d] * 0.25f;          // fold 1/sqrt(D)
        KK[d] = pr[192 + h * 16 + d];
    }
    float sq2 = 0.f, sk2 = 0.f;
#pragma unroll
    for (int p = 0; p < 4; p++) {
        const float* qp = pr + 576 + h * 12 + p * 3;
        float x = qp[0], y = qp[1], zz = qp[2];
        float gx = R0 * x + R1 * y + R2 * zz + t0;
        float gy = R3 * x + R4 * y + R5 * zz + t1;
        float gz = R6 * x + R7 * y + R8 * zz + t2;
        QQ[16 + p * 3 + 0] = 2.f * cg * gx;
        QQ[16 + p * 3 + 1] = 2.f * cg * gy;
        QQ[16 + p * 3 + 2] = 2.f * cg * gz;
        sq2 += gx * gx + gy * gy + gz * gz;
        const float* kp = pr + 720 + h * 12 + p * 3;
        x = kp[0]; y = kp[1]; zz = kp[2];
        gx = R0 * x + R1 * y + R2 * zz + t0;
        gy = R3 * x + R4 * y + R5 * zz + t1;
        gz = R6 * x + R7 * y + R8 * zz + t2;
        KK[16 + p * 3 + 0] = gx; KK[16 + p * 3 + 1] = gy; KK[16 + p * 3 + 2] = gz;
        sk2 += gx * gx + gy * gy + gz * gz;
    }
    QQ[28] = -cg;       KK[28] = sk2;
    QQ[29] = -cg * sq2; KK[29] = 1.f;
    QQ[30] = 0.f; QQ[31] = 0.f; KK[30] = 0.f; KK[31] = 0.f;
    // pack [v | tv] for kagg
    float* vt = VTb + (size_t)row * 480 + h * 40;
#pragma unroll
    for (int d = 0; d < 16; d++) vt[d] = pr[384 + h * 16 + d];
#pragma unroll
    for (int p = 0; p < 8; p++) {
        const float* vp = pr + 864 + h * 24 + p * 3;
        float x = vp[0], y = vp[1], zz = vp[2];
        vt[16 + p * 3 + 0] = R0 * x + R1 * y + R2 * zz + t0;
        vt[16 + p * 3 + 1] = R3 * x + R4 * y + R5 * zz + t1;
        vt[16 + p * 3 + 2] = R6 * x + R7 * y + R8 * zz + t2;
    }
}

// ---------------- K4: score GEMM + per-row block maxes ----------------
__global__ __launch_bounds__(256) void kscore() {
    __shared__ float As[32][68];
    __shared__ float Bs[32][68];
    int t = threadIdx.x;
    int bh = blockIdx.z, b = bh / 12, h = bh % 12;
    int i0 = blockIdx.y * 64, j0 = blockIdx.x * 64;
#pragma unroll
    for (int s = 0; s < 2; s++) {
        int idx = t + s * 256;
        int r = idx >> 3, c4 = (idx & 7) * 4;
        float4 va = *(const float4*)(QQb + (size_t)(b * 512 + i0 + r) * 384 + h * 32 + c4);
        As[c4][r] = va.x; As[c4 + 1][r] = va.y; As[c4 + 2][r] = va.z; As[c4 + 3][r] = va.w;
        float4 vb = *(const float4*)(KKb + (size_t)(b * 512 + j0 + r) * 384 + h * 32 + c4);
        Bs[c4][r] = vb.x; Bs[c4 + 1][r] = vb.y; Bs[c4 + 2][r] = vb.z; Bs[c4 + 3][r] = vb.w;
    }
    __syncthreads();
    int tx = t & 15, ty = t >> 4;
    float acc[4][4] = {};
#pragma unroll
    for (int kk = 0; kk < 32; kk++) {
        float4 ra = *(const float4*)(&As[kk][ty * 4]);
        float4 rb = *(const float4*)(&Bs[kk][tx * 4]);
        acc[0][0] += ra.x * rb.x; acc[0][1] += ra.x * rb.y; acc[0][2] += ra.x * rb.z; acc[0][3] += ra.x * rb.w;
        acc[1][0] += ra.y * rb.x; acc[1][1] += ra.y * rb.y; acc[1][2] += ra.y * rb.z; acc[1][3] += ra.y * rb.w;
        acc[2][0] += ra.z * rb.x; acc[2][1] += ra.z * rb.y; acc[2][2] += ra.z * rb.z; acc[2][3] += ra.z * rb.w;
        acc[3][0] += ra.w * rb.x; acc[3][1] += ra.w * rb.y; acc[3][2] += ra.w * rb.z; acc[3][3] += ra.w * rb.w;
    }
#pragma unroll
    for (int u = 0; u < 4; u++) {
        float4 o = make_float4(acc[u][0], acc[u][1], acc[u][2], acc[u][3]);
        *(float4*)(SCA + ((size_t)bh * 512 + i0 + ty * 4 + u) * 512 + j0 + tx * 4) = o;
    }
    // per-row max over this 64-j block (reduce across 16 tx threads)
#pragma unroll
    for (int u = 0; u < 4; u++) {
        float rm = fmaxf(fmaxf(acc[u][0], acc[u][1]), fmaxf(acc[u][2], acc[u][3]));
#pragma unroll
        for (int o = 8; o; o >>= 1) rm = fmaxf(rm, __shfl_xor_sync(0xffffffffu, rm, o));
        if (tx == 0)
            SMAXPART[((size_t)bh * 512 + i0 + ty * 4 + u) * 8 + blockIdx.x] = rm;
    }
}

// ---------------- K5: single-pass fused attention per (b,i) ----------------
// dyn smem: zs 128*132 (reused as part [12][520]) | wbT 1536 | smaxs 16 | rinv 16 | redu 48
__global__ __launch_bounds__(512)
void kattn(const float* __restrict__ z, const float* __restrict__ wb) {
    extern __shared__ float sm[];
    float* zs    = sm;           // 16896
    float* wbT   = sm + 16896;   // 1536
    float* smaxs = sm + 18432;   // 16
    float* rinv  = sm + 18448;   // 16
    float* redu  = sm + 18464;   // 48 (total 18512 -> alloc 18528)
    int t = threadIdx.x;
    int l = t & 31, w = t >> 5;
    int jr = w & 3, g = w >> 2;          // j-quarter, head-triple group
    int row = blockIdx.x, b = row >> 9, i = row & 511;
    const float* zrow = z + (size_t)row * 65536;
    const size_t pl = (size_t)262144;
    const size_t base = (size_t)(b * 12) * pl + (size_t)i * 512;

    for (int e = t; e < 1536; e += 512) {
        int h = e >> 7, c = e & 127;
        wbT[e] = wb[c * 12 + h];
    }
    if (t < 12) {
        const float* sp = SMAXPART + ((size_t)(b * 12 + t) * 512 + i) * 8;
        float m = sp[0];
#pragma unroll
        for (int k = 1; k < 8; k++) m = fmaxf(m, sp[k]);
        smaxs[t] = 0.5773502691896258f * m;
    }

    const float4* w0 = (const float4*)(wbT + g * 128);
    const float4* w1 = (const float4*)(wbT + (g + 4) * 128);
    const float4* w2 = (const float4*)(wbT + (g + 8) * 128);
    float acc[3][4] = {};
    float sh0 = 0.f, sh1 = 0.f, sh2 = 0.f;

    for (int tile = 0; tile < 4; tile++) {
#pragma unroll
        for (int s = 0; s < 8; s++) {
            int idx = t + s * 512;
            int r = idx >> 5, c4 = idx & 31;
            *(float4*)(zs + r * 132 + c4 * 4) =
                *(const float4*)(zrow + (size_t)(tile * 128 + r) * 128 + c4 * 4);
        }
        __syncthreads();    // zs (and first-tile wbT/smaxs) ready
        // ---- logits + exp for my j = tile*128 + jr*32 + l ----
        int jl = jr * 32 + l;
        float a0 = 0.f, a1 = 0.f, a2 = 0.f;
        const float4* zv4 = (const float4*)(zs + jl * 132);
#pragma unroll
        for (int c4 = 0; c4 < 32; c4++) {
            float4 zq = zv4[c4];
            float4 x0 = w0[c4], x1 = w1[c4], x2 = w2[c4];
            a0 += zq.x * x0.x + zq.y * x0.y + zq.z * x0.z + zq.w * x0.w;
            a1 += zq.x * x1.x + zq.y * x1.y + zq.z * x1.z + zq.w * x1.w;
            a2 += zq.x * x2.x + zq.y * x2.y + zq.z * x2.z + zq.w * x2.w;
        }
        int j = tile * 128 + jl;
        const float WL = 0.5773502691896258f;
        float e0 = __expf(WL * (a0 + SCA[base + (size_t)g * pl + j])       - smaxs[g]);
        float e1 = __expf(WL * (a1 + SCA[base + (size_t)(g + 4) * pl + j]) - smaxs[g + 4]);
        float e2 = __expf(WL * (a2 + SCA[base + (size_t)(g + 8) * pl + j]) - smaxs[g + 8]);
        SCA[base + (size_t)g * pl + j]       = e0;
        SCA[base + (size_t)(g + 4) * pl + j] = e1;
        SCA[base + (size_t)(g + 8) * pl + j] = e2;
        sh0 += e0; sh1 += e1; sh2 += e2;
        // ---- aggregate my 32 j via shfl (weights live in this warp) ----
#pragma unroll 4
        for (int jj = 0; jj < 32; jj++) {
            float f0 = __shfl_sync(0xffffffffu, e0, jj);
            float f1 = __shfl_sync(0xffffffffu, e1, jj);
            float f2 = __shfl_sync(0xffffffffu, e2, jj);
            float4 zq = *(const float4*)(zs + (jr * 32 + jj) * 132 + l * 4);
            acc[0][0] += f0 * zq.x; acc[0][1] += f0 * zq.y; acc[0][2] += f0 * zq.z; acc[0][3] += f0 * zq.w;
            acc[1][0] += f1 * zq.x; acc[1][1] += f1 * zq.y; acc[1][2] += f1 * zq.z; acc[1][3] += f1 * zq.w;
            acc[2][0] += f2 * zq.x; acc[2][1] += f2 * zq.y; acc[2][2] += f2 * zq.z; acc[2][3] += f2 * zq.w;
        }
        __syncthreads();    // all reads of zs done before next tile's stores
    }

    // ---- warp-reduce per-head sums ----
#pragma unroll
    for (int o = 16; o; o >>= 1) {
        sh0 += __shfl_xor_sync(0xffffffffu, sh0, o);
        sh1 += __shfl_xor_sync(0xffffffffu, sh1, o);
        sh2 += __shfl_xor_sync(0xffffffffu, sh2, o);
    }
    if (l == 0) { redu[w * 3 + 0] = sh0; redu[w * 3 + 1] = sh1; redu[w * 3 + 2] = sh2; }
    // ---- partials into smem (reuse zs), layout [h][520], STS.128 conflict-free ----
    float* part = zs;
#pragma unroll
    for (int k = 0; k < 3; k++) {
        int h = g + k * 4;
        *(float4*)(part + h * 520 + jr * 128 + l * 4) =
            make_float4(acc[k][0], acc[k][1], acc[k][2], acc[k][3]);
    }
    __syncthreads();
    if (t < 12) {
        int h = t, gg = h & 3, k = h >> 2;
        float s = redu[(gg * 4 + 0) * 3 + k] + redu[(gg * 4 + 1) * 3 + k]
                + redu[(gg * 4 + 2) * 3 + k] + redu[(gg * 4 + 3) * 3 + k];
        float r = 1.f / s;
        rinv[h] = r;
        RINVb[(size_t)(b * 12 + h) * 512 + i] = r;
    }
    __syncthreads();
    float* cat = CATb + (size_t)row * 2112;
#pragma unroll
    for (int u = 0; u < 3; u++) {
        int e = t + u * 512;
        int h = e >> 7, d = e & 127;
        float s = part[h * 520 + d] + part[h * 520 + 128 + d]
                + part[h * 520 + 256 + d] + part[h * 520 + 384 + d];
        cat[h * 128 + d] = s * rinv[h];
    }
}

// ---------------- K6: value aggregation GEMMs  E[bh] x [v|tv], normalize by rinv ----------------
__global__ __launch_bounds__(256) void kagg() {
    __shared__ float As[64 * 68];   // [i][j], pitch 68
    __shared__ float Bs[64 * 41];   // [j][c], c<16 -> v, else tv
    int t = threadIdx.x;
    int bh = blockIdx.y, b = bh / 12, h = bh % 12;
    int i0 = blockIdx.x * 64;
    int il = t & 63, cp = t >> 6;
    float acc[10] = {};
    for (int jt = 0; jt < 8; jt++) {
        __syncthreads();
#pragma unroll
        for (int s = 0; s < 4; s++) {
            int idx = t + s * 256;
            int r = idx >> 4, j4 = (idx & 15) * 4;
            float4 v = *(const float4*)(SCA + ((size_t)bh * 512 + i0 + r) * 512 + jt * 64 + j4);
            *(float4*)(As + r * 68 + j4) = v;
        }
#pragma unroll
        for (int s = 0; s < 10; s++) {
            int idx = t + s * 256;
            int jj = idx / 40, c = idx - jj * 40;
            Bs[jj * 41 + c] = VTb[(size_t)(b * 512 + jt * 64 + jj) * 480 + h * 40 + c];
        }
        __syncthreads();
        const float4* a4 = (const float4*)(As + il * 68);
#pragma unroll
        for (int j4 = 0; j4 < 16; j4++) {
            float4 av = a4[j4];
#pragma unroll
            for (int u = 0; u < 4; u++) {
                float a = u == 0 ? av.x : u == 1 ? av.y : u == 2 ? av.z : av.w;
                const float* brow = Bs + (j4 * 4 + u) * 41 + cp;
#pragma unroll
                for (int cc = 0; cc < 10; cc++) acc[cc] += a * brow[cc * 4];
            }
        }
    }
    float rv = RINVb[(size_t)bh * 512 + i0 + il];
    size_t crow = (size_t)(b * 512 + i0 + il);
#pragma unroll
    for (int cc = 0; cc < 10; cc++) {
        int col = cp + cc * 4;
        float v = acc[cc] * rv;
        if (col < 16) CATb[crow * 2112 + 1536 + h * 16 + col] = v;
        else          OHP[crow * 288 + h * 24 + (col - 16)] = v;
    }
}

// ---------------- K7: rigid invert + norms ----------------
__global__ void kepi(const float* __restrict__ rots, const float* __restrict__ trans) {
    __shared__ float R[9], T[3];
    int row = blockIdx.x, t = threadIdx.x;   // 96 threads
    if (t < 9) R[t] = rots[row * 9 + t];
    if (t < 3) T[t] = trans[row * 3 + t];
    __syncthreads();
    size_t base = (size_t)row * 288 + t * 3;
    float gx = OHP[base + 0] - T[0];
    float gy = OHP[base + 1] - T[1];
    float gz = OHP[base + 2] - T[2];
    float lx = R[0] * gx + R[3] * gy + R[6] * gz;
    float ly = R[1] * gx + R[4] * gy + R[7] * gz;
    float lz = R[2] * gx + R[5] * gy + R[8] * gz;
    float* cat = CATb + (size_t)row * 2112;
    cat[1728 + t * 3 + 0] = lx;
    cat[1728 + t * 3 + 1] = ly;
    cat[1728 + t * 3 + 2] = lz;
    cat[2016 + t] = sqrtf(lx * lx + ly * ly + lz * lz);
}

extern "C" void kernel_launch(void* const* d_in, const int* in_sizes, int n_in,
                              void* d_out, int out_size) {
    const float* s_i   = (const float*)d_in[0];
    const float* z_ij  = (const float*)d_in[1];
    const float* rots  = (const float*)d_in[2];
    const float* trans = (const float*)d_in[3];
    const float* wq    = (const float*)d_in[4];
    const float* wk    = (const float*)d_in[5];
    const float* wv    = (const float*)d_in[6];
    const float* wqp   = (const float*)d_in[7];
    const float* wkp   = (const float*)d_in[8];
    const float* wvp   = (const float*)d_in[9];
    const float* wb    = (const float*)d_in[10];
    const float* gamma = (const float*)d_in[11];
    const float* wout  = (const float*)d_in[12];
    const float* bout  = (const float*)d_in[13];
    float* out = (float*)d_out;

    float* dWPROJ; cudaGetSymbolAddress((void**)&dWPROJ, WPROJ);
    float* dPROJ;  cudaGetSymbolAddress((void**)&dPROJ, PROJ);
    float* dCAT;   cudaGetSymbolAddress((void**)&dCAT, CATb);
    float* dOUTP;  cudaGetSymbolAddress((void**)&dOUTP, OUTPART);

    static int smem_set = 0;
    const int KATTN_SMEM = 18528 * 4;
    if (!smem_set) {
        cudaFuncSetAttribute(kattn, cudaFuncAttributeMaxDynamicSharedMemorySize, KATTN_SMEM);
        smem_set = 1;
    }

    kpack<<<1728, 256>>>(wq, wk, wv, wqp, wkp, wvp);
    {   // PROJ = s_i @ WPROJ : 1024 x 1152 x 384
        dim3 g(1152 / 64, 1024 / 64, 1);
        sgemm_k<<<g, 256>>>(s_i, dWPROJ, dPROJ, 1024, 1152, 384, 384, nullptr);
    }
    ktransform<<<1024, 32>>>(rots, trans, gamma);
    {
        dim3 g(8, 8, 24);
        kscore<<<g, 256>>>();
    }
    kattn<<<1024, 512, KATTN_SMEM>>>(z_ij, wb);
    {
        dim3 g(8, 24);
        kagg<<<g, 256>>>();
    }
    kepi<<<1024, 96>>>(rots, trans);
    {   // OUTPART[s] = CAT @ wout over K-slice s : 1024 x 384 x (4 x 528)
        dim3 g(384 / 64, 1024 / 64, 4);
        sgemm_k<<<g, 256>>>(dCAT, wout, dOUTP, 1024, 384, 2112, 528, nullptr);
    }
    kreduce<<<1536, 256>>>(out, bout);
}